// round 4
// baseline (speedup 1.0000x reference)
#include <cuda_runtime.h>
#include <cuda_bf16.h>
#include <cstdint>

// ---------------------------------------------------------------------------
// AttentionSampling: B=4, SQ=2048, SK=8192, D=H=512, F=4, fp32.
// GEMMs via mma.sync bf16 hi/lo 3-pass, fp32 accum. Activations pre-split to
// bf16 hi/lo so the GEMM mainloop is pure cp.async + ldmatrix + HMMA.
// ---------------------------------------------------------------------------

#define DD 512
#define NQ  8192
#define NKV 32768
#define EPS 1e-5f

// fp32 scratch planes
#define F_Q   0
#define F_K   (F_Q  + (size_t)NQ  * DD)
#define F_V   (F_K  + (size_t)NKV * DD)
#define F_O1  (F_V  + (size_t)NKV * DD)
#define F_FF  (F_O1 + (size_t)NQ  * DD)
#define F_TOT (F_FF + (size_t)NQ  * DD)
__device__ float g_scratch[F_TOT];

// bf16 hi/lo activation planes
#define B_QH  0
#define B_QL  (B_QH  + (size_t)NQ  * DD)
#define B_KH  (B_QL  + (size_t)NQ  * DD)
#define B_KL  (B_KH  + (size_t)NKV * DD)
#define B_VH  (B_KL  + (size_t)NKV * DD)
#define B_VL  (B_VH  + (size_t)NKV * DD)
#define B_O1H (B_VL  + (size_t)NKV * DD)
#define B_O1L (B_O1H + (size_t)NQ  * DD)
#define B_HH  (B_O1L + (size_t)NQ  * DD)
#define B_HL  (B_HH  + (size_t)NQ  * DD)
#define B_TOT (B_HL  + (size_t)NQ  * DD)
__device__ __nv_bfloat16 g_act[B_TOT];

// 5 weights x (hi,lo) x 512x512 bf16, stored [N][K] (transposed)
__device__ __nv_bfloat16 g_wsplit[5u * 2u * 512u * 512u];

// ---------------------------------------------------------------------------
// PTX helpers (base sm_100-legal)
// ---------------------------------------------------------------------------
__device__ __forceinline__ uint32_t smem_u32(const void* p) {
    uint32_t a;
    asm("{ .reg .u64 t; cvta.to.shared.u64 t, %1; cvt.u32.u64 %0, t; }"
        : "=r"(a) : "l"(p));
    return a;
}
__device__ __forceinline__ void ldsm_x4(uint32_t* r, uint32_t addr) {
    asm volatile("ldmatrix.sync.aligned.m8n8.x4.shared.b16 {%0,%1,%2,%3}, [%4];"
                 : "=r"(r[0]), "=r"(r[1]), "=r"(r[2]), "=r"(r[3]) : "r"(addr));
}
__device__ __forceinline__ void mma16816(float* c, const uint32_t* a, const uint32_t* b) {
    asm volatile(
        "mma.sync.aligned.m16n8k16.row.col.f32.bf16.bf16.f32 "
        "{%0,%1,%2,%3}, {%4,%5,%6,%7}, {%8,%9}, {%0,%1,%2,%3};"
        : "+f"(c[0]), "+f"(c[1]), "+f"(c[2]), "+f"(c[3])
        : "r"(a[0]), "r"(a[1]), "r"(a[2]), "r"(a[3]), "r"(b[0]), "r"(b[1]));
}
__device__ __forceinline__ void cp16(uint32_t saddr, const void* g) {
    asm volatile("cp.async.cg.shared.global [%0], [%1], 16;"
                 :: "r"(saddr), "l"(g) : "memory");
}
__device__ __forceinline__ void cp_commit() {
    asm volatile("cp.async.commit_group;" ::: "memory");
}

__device__ __forceinline__ void split_bf16(float x, __nv_bfloat16& h, __nv_bfloat16& l) {
    h = __float2bfloat16(x);
    l = __float2bfloat16(x - __bfloat162float(h));
}

// ---------------------------------------------------------------------------
// Batched weight prep: W[k][n] fp32 -> Th[n][k], Tl[n][k] bf16 (5 weights)
// ---------------------------------------------------------------------------
__global__ void prep_weight5(
    const float* w0, const float* w1, const float* w2, const float* w3, const float* w4,
    __nv_bfloat16* base)
{
    const float* Ws[5] = {w0, w1, w2, w3, w4};
    const size_t WSZ = 512u * 512u;
    const float* W = Ws[blockIdx.z];
    __nv_bfloat16* Th = base + (size_t)blockIdx.z * 2u * WSZ;
    __nv_bfloat16* Tl = Th + WSZ;

    __shared__ float t[32][33];
    const int bx = blockIdx.x * 32, by = blockIdx.y * 32;
    const int tx = threadIdx.x, ty = threadIdx.y; // 32 x 8
#pragma unroll
    for (int i = 0; i < 32; i += 8)
        t[ty + i][tx] = W[(size_t)(by + ty + i) * DD + bx + tx];
    __syncthreads();
#pragma unroll
    for (int i = 0; i < 32; i += 8) {
        float x = t[tx][ty + i]; // W[by+tx][bx+ty+i]
        __nv_bfloat16 h, l;
        split_bf16(x, h, l);
        size_t o = (size_t)(bx + ty + i) * DD + by + tx;
        Th[o] = h;
        Tl[o] = l;
    }
}

// ---------------------------------------------------------------------------
// fp32 -> bf16 hi/lo split (vectorized)
// ---------------------------------------------------------------------------
__global__ void __launch_bounds__(256) f32_to_hl(
    const float4* __restrict__ src, uint2* __restrict__ dh, uint2* __restrict__ dl)
{
    const int i = blockIdx.x * 256 + threadIdx.x;
    float4 x = src[i];
    __nv_bfloat16 hx, hy, hz, hw, lx, ly, lz, lw;
    split_bf16(x.x, hx, lx); split_bf16(x.y, hy, ly);
    split_bf16(x.z, hz, lz); split_bf16(x.w, hw, lw);
    __nv_bfloat162 h01, h23, l01, l23;
    h01.x = hx; h01.y = hy; h23.x = hz; h23.y = hw;
    l01.x = lx; l01.y = ly; l23.x = lz; l23.y = lw;
    uint2 hv, lv;
    hv.x = *(uint32_t*)&h01; hv.y = *(uint32_t*)&h23;
    lv.x = *(uint32_t*)&l01; lv.y = *(uint32_t*)&l23;
    dh[i] = hv;
    dl[i] = lv;
}

// ---------------------------------------------------------------------------
// HMMA GEMM: C[M,512] = act(A[M,512] @ W[512,512] + bias)
// A given as bf16 hi/lo planes [M][512]; W as bf16 hi/lo [N=512][K=512].
// BM=128, BN=128, BK=32, 256 thr (8 warps 2m x 4n; warp tile 64x32).
// 4-stage cp.async pipeline; rows padded to 80B for conflict-free ldmatrix.
// OUT_HL: write bf16 hi/lo planes instead of fp32.
// ---------------------------------------------------------------------------
#define BKC 32
#define NCH (DD / BKC)          // 16
#define RSTRB 80                // bytes per smem row (32 bf16 + 16B pad)
#define PLANE (128 * RSTRB)     // 10240
#define SG_AH 0
#define SG_AL (1 * PLANE)
#define SG_BH (2 * PLANE)
#define SG_BL (3 * PLANE)
#define SG_SZ (4 * PLANE)       // 40960
#define STAGES 4
#define GEMM_SMEM (STAGES * SG_SZ) // 163840

template <bool RELU, bool OUT_HL>
__global__ void __launch_bounds__(256, 1) gemm_hl(
    const __nv_bfloat16* __restrict__ Ah, const __nv_bfloat16* __restrict__ Al,
    const __nv_bfloat16* __restrict__ Bh, const __nv_bfloat16* __restrict__ Bl,
    const float* __restrict__ bias, float* __restrict__ C,
    __nv_bfloat16* __restrict__ Ch, __nv_bfloat16* __restrict__ Cl)
{
    extern __shared__ char sm[];
    const uint32_t sb = smem_u32(sm);

    const int tid = threadIdx.x;
    const int lane = tid & 31, wid = tid >> 5;
    const int wm = (wid & 1) * 64;
    const int wn = (wid >> 1) * 32;
    const int bm = blockIdx.y * 128;
    const int bn = blockIdx.x * 128;

    float acc[4][4][4];
#pragma unroll
    for (int i = 0; i < 4; i++)
#pragma unroll
        for (int j = 0; j < 4; j++)
#pragma unroll
            for (int t = 0; t < 4; t++) acc[i][j][t] = 0.f;

    // cp.async mapping: 512 16B segs per plane; thread does 2 per plane
    const int r0id = tid, r1id = tid + 256;
    const int row0 = r0id >> 2, seg0 = r0id & 3;
    const int row1 = r1id >> 2, seg1 = r1id & 3;

    auto load_stage = [&](int c, int buf) {
        const uint32_t st = sb + buf * SG_SZ;
        const int kc = c * BKC;
        {
            uint32_t so = (uint32_t)row0 * RSTRB + seg0 * 16;
            size_t ga = (size_t)(bm + row0) * DD + kc + seg0 * 8;
            size_t gb = (size_t)(bn + row0) * DD + kc + seg0 * 8;
            cp16(st + SG_AH + so, Ah + ga);
            cp16(st + SG_AL + so, Al + ga);
            cp16(st + SG_BH + so, Bh + gb);
            cp16(st + SG_BL + so, Bl + gb);
        }
        {
            uint32_t so = (uint32_t)row1 * RSTRB + seg1 * 16;
            size_t ga = (size_t)(bm + row1) * DD + kc + seg1 * 8;
            size_t gb = (size_t)(bn + row1) * DD + kc + seg1 * 8;
            cp16(st + SG_AH + so, Ah + ga);
            cp16(st + SG_AL + so, Al + ga);
            cp16(st + SG_BH + so, Bh + gb);
            cp16(st + SG_BL + so, Bl + gb);
        }
        cp_commit();
    };

    // ldmatrix lane addressing (validated round 3)
    const int a_r = wm + (lane & 15);
    const int a_cb = (lane >> 4) * 16;
    const int b_r = wn + ((lane >> 4) << 3) + (lane & 7);
    const int b_cb = ((lane >> 3) & 1) * 16;

    uint32_t ah[2][4][4], al[2][4][4], bh[2][2][4], bl[2][2][4];

#define LOADFRAG(ST, KS, DST) do {                                          \
        const uint32_t kb = (KS) * 32;                                      \
        _Pragma("unroll")                                                   \
        for (int i = 0; i < 4; i++) {                                       \
            uint32_t off = (uint32_t)(a_r + i * 16) * RSTRB + kb + a_cb;    \
            ldsm_x4(ah[DST][i], (ST) + SG_AH + off);                        \
            ldsm_x4(al[DST][i], (ST) + SG_AL + off);                        \
        }                                                                   \
        _Pragma("unroll")                                                   \
        for (int jp = 0; jp < 2; jp++) {                                    \
            uint32_t off = (uint32_t)(b_r + jp * 16) * RSTRB + kb + b_cb;   \
            ldsm_x4(bh[DST][jp], (ST) + SG_BH + off);                       \
            ldsm_x4(bl[DST][jp], (ST) + SG_BL + off);                       \
        }                                                                   \
    } while (0)

    auto compute = [&](int buf) {
        const uint32_t st = sb + buf * SG_SZ;
        LOADFRAG(st, 0, 0);
#pragma unroll
        for (int ks = 0; ks < 2; ks++) {
            if (ks == 0) LOADFRAG(st, 1, 1);
            // pass-major: 16 independent accs between same-acc reuse
#pragma unroll
            for (int i = 0; i < 4; i++)
#pragma unroll
                for (int j = 0; j < 4; j++)
                    mma16816(acc[i][j], ah[ks][i], &bh[ks][j >> 1][(j & 1) * 2]);
#pragma unroll
            for (int i = 0; i < 4; i++)
#pragma unroll
                for (int j = 0; j < 4; j++)
                    mma16816(acc[i][j], ah[ks][i], &bl[ks][j >> 1][(j & 1) * 2]);
#pragma unroll
            for (int i = 0; i < 4; i++)
#pragma unroll
                for (int j = 0; j < 4; j++)
                    mma16816(acc[i][j], al[ks][i], &bh[ks][j >> 1][(j & 1) * 2]);
        }
    };

    // prologue: fill 3 stages
    load_stage(0, 0);
    load_stage(1, 1);
    load_stage(2, 2);

#pragma unroll 1
    for (int c = 0; c < NCH; c++) {
        asm volatile("cp.async.wait_group 2;" ::: "memory");
        __syncthreads();
        if (c + 3 < NCH) load_stage(c + 3, (c + 3) & 3);
        compute(c & 3);
    }

    // epilogue
    const int crow = lane >> 2, ccol = (lane & 3) * 2;
#pragma unroll
    for (int i = 0; i < 4; i++) {
        const int r0 = bm + wm + i * 16 + crow;
#pragma unroll
        for (int j = 0; j < 4; j++) {
            const int col = bn + wn + j * 8 + ccol;
            float2 bv = *(const float2*)(bias + col);
            float2 o0, o1;
            o0.x = acc[i][j][0] + bv.x; o0.y = acc[i][j][1] + bv.y;
            o1.x = acc[i][j][2] + bv.x; o1.y = acc[i][j][3] + bv.y;
            if (RELU) {
                o0.x = fmaxf(o0.x, 0.f); o0.y = fmaxf(o0.y, 0.f);
                o1.x = fmaxf(o1.x, 0.f); o1.y = fmaxf(o1.y, 0.f);
            }
            if (OUT_HL) {
                __nv_bfloat162 h2, l2;
                split_bf16(o0.x, h2.x, l2.x); split_bf16(o0.y, h2.y, l2.y);
                *(__nv_bfloat162*)(Ch + (size_t)r0 * DD + col) = h2;
                *(__nv_bfloat162*)(Cl + (size_t)r0 * DD + col) = l2;
                split_bf16(o1.x, h2.x, l2.x); split_bf16(o1.y, h2.y, l2.y);
                *(__nv_bfloat162*)(Ch + (size_t)(r0 + 8) * DD + col) = h2;
                *(__nv_bfloat162*)(Cl + (size_t)(r0 + 8) * DD + col) = l2;
            } else {
                *(float2*)(C + (size_t)r0 * DD + col) = o0;
                *(float2*)(C + (size_t)(r0 + 8) * DD + col) = o1;
            }
        }
    }
}

// ---------------------------------------------------------------------------
// warp reduction
// ---------------------------------------------------------------------------
__device__ __forceinline__ float warp_sum(float x) {
#pragma unroll
    for (int o = 16; o > 0; o >>= 1) x += __shfl_xor_sync(0xffffffffu, x, o);
    return x;
}

// ---------------------------------------------------------------------------
// Fused attention downsampling + residual + LN1; emits fp32 + bf16 hi/lo out1.
// ---------------------------------------------------------------------------
__global__ void __launch_bounds__(256) attn_ln_kernel(
    const float* __restrict__ q, const float* __restrict__ k,
    const float* __restrict__ v, const float* __restrict__ gamma,
    const float* __restrict__ beta, float* __restrict__ out,
    __nv_bfloat16* __restrict__ outh, __nv_bfloat16* __restrict__ outl)
{
    const int row = blockIdx.x;
    const float* qr = q + (size_t)row * DD;
    const float* kr = k + (size_t)row * 4 * DD;
    const float* vr = v + (size_t)row * 4 * DD;
    const int tid = threadIdx.x;
    const int lane = tid & 31, wid = tid >> 5;

    float q0 = qr[tid], q1 = qr[tid + 256];

    float p[4];
#pragma unroll
    for (int f = 0; f < 4; f++)
        p[f] = q0 * kr[f * DD + tid] + q1 * kr[f * DD + tid + 256];

    __shared__ float red[4][8];
#pragma unroll
    for (int f = 0; f < 4; f++) {
        float s = warp_sum(p[f]);
        if (lane == 0) red[f][wid] = s;
    }
    __syncthreads();
    __shared__ float wsh[4];
    if (tid < 4) {
        float s = 0.f;
#pragma unroll
        for (int i = 0; i < 8; i++) s += red[tid][i];
        wsh[tid] = s;
    }
    __syncthreads();
    const float w0 = wsh[0], w1 = wsh[1], w2 = wsh[2], w3 = wsh[3];

    float r0 = q0 + w0 * vr[tid]          + w1 * vr[DD + tid]
                  + w2 * vr[2 * DD + tid] + w3 * vr[3 * DD + tid];
    float r1 = q1 + w0 * vr[tid + 256]          + w1 * vr[DD + tid + 256]
                  + w2 * vr[2 * DD + tid + 256] + w3 * vr[3 * DD + tid + 256];

    float s = warp_sum(r0 + r1);
    float ss = warp_sum(r0 * r0 + r1 * r1);
    __shared__ float rs[8], rss[8];
    if (lane == 0) { rs[wid] = s; rss[wid] = ss; }
    __syncthreads();
    __shared__ float mv[2];
    if (tid == 0) {
        float S = 0.f, SS = 0.f;
#pragma unroll
        for (int i = 0; i < 8; i++) { S += rs[i]; SS += rss[i]; }
        float mean = S * (1.f / 512.f);
        float var = SS * (1.f / 512.f) - mean * mean;
        mv[0] = mean; mv[1] = rsqrtf(var + EPS);
    }
    __syncthreads();
    const float mean = mv[0], inv = mv[1];
    const size_t off = (size_t)row * DD;
    float y0 = (r0 - mean) * inv * gamma[tid]       + beta[tid];
    float y1 = (r1 - mean) * inv * gamma[tid + 256] + beta[tid + 256];
    out[off + tid] = y0;
    out[off + tid + 256] = y1;
    __nv_bfloat16 h, l;
    split_bf16(y0, h, l); outh[off + tid] = h;       outl[off + tid] = l;
    split_bf16(y1, h, l); outh[off + tid + 256] = h; outl[off + tid + 256] = l;
}

// ---------------------------------------------------------------------------
// Fused residual + LayerNorm2 -> output
// ---------------------------------------------------------------------------
__global__ void __launch_bounds__(256) resid_ln_kernel(
    const float* __restrict__ a, const float* __restrict__ f,
    const float* __restrict__ gamma, const float* __restrict__ beta,
    float* __restrict__ out)
{
    const int row = blockIdx.x;
    const int tid = threadIdx.x;
    const int lane = tid & 31, wid = tid >> 5;
    const size_t off = (size_t)row * DD;

    float r0 = a[off + tid]       + f[off + tid];
    float r1 = a[off + tid + 256] + f[off + tid + 256];

    float s = warp_sum(r0 + r1);
    float ss = warp_sum(r0 * r0 + r1 * r1);
    __shared__ float rs[8], rss[8];
    if (lane == 0) { rs[wid] = s; rss[wid] = ss; }
    __syncthreads();
    __shared__ float mv[2];
    if (tid == 0) {
        float S = 0.f, SS = 0.f;
#pragma unroll
        for (int i = 0; i < 8; i++) { S += rs[i]; SS += rss[i]; }
        float mean = S * (1.f / 512.f);
        float var = SS * (1.f / 512.f) - mean * mean;
        mv[0] = mean; mv[1] = rsqrtf(var + EPS);
    }
    __syncthreads();
    const float mean = mv[0], inv = mv[1];
    out[off + tid]       = (r0 - mean) * inv * gamma[tid]       + beta[tid];
    out[off + tid + 256] = (r1 - mean) * inv * gamma[tid + 256] + beta[tid + 256];
}

// ---------------------------------------------------------------------------
// Launch
// ---------------------------------------------------------------------------
extern "C" void kernel_launch(void* const* d_in, const int* in_sizes, int n_in,
                              void* d_out, int out_size)
{
    const float* query  = (const float*)d_in[0];
    const float* key    = (const float*)d_in[1];
    const float* value  = (const float*)d_in[2];
    const float* w_q    = (const float*)d_in[3];
    const float* b_q    = (const float*)d_in[4];
    const float* w_k    = (const float*)d_in[5];
    const float* b_k    = (const float*)d_in[6];
    const float* w_v    = (const float*)d_in[7];
    const float* b_v    = (const float*)d_in[8];
    const float* ln1_g  = (const float*)d_in[9];
    const float* ln1_b  = (const float*)d_in[10];
    const float* ln2_g  = (const float*)d_in[11];
    const float* ln2_b  = (const float*)d_in[12];
    const float* ffn_w1 = (const float*)d_in[13];
    const float* ffn_b1 = (const float*)d_in[14];
    const float* ffn_w2 = (const float*)d_in[15];
    const float* ffn_b2 = (const float*)d_in[16];
    float* out = (float*)d_out;

    void* sp = nullptr;
    cudaGetSymbolAddress(&sp, g_scratch);
    float* s = (float*)sp;
    float* g_q    = s + F_Q;
    float* g_k    = s + F_K;
    float* g_v    = s + F_V;
    float* g_out1 = s + F_O1;
    float* g_ffn  = s + F_FF;

    void* ap = nullptr;
    cudaGetSymbolAddress(&ap, g_act);
    __nv_bfloat16* a = (__nv_bfloat16*)ap;
    __nv_bfloat16* qh  = a + B_QH;  __nv_bfloat16* ql  = a + B_QL;
    __nv_bfloat16* kh  = a + B_KH;  __nv_bfloat16* kl  = a + B_KL;
    __nv_bfloat16* vh  = a + B_VH;  __nv_bfloat16* vl  = a + B_VL;
    __nv_bfloat16* o1h = a + B_O1H; __nv_bfloat16* o1l = a + B_O1L;
    __nv_bfloat16* hh  = a + B_HH;  __nv_bfloat16* hl  = a + B_HL;

    void* wp = nullptr;
    cudaGetSymbolAddress(&wp, g_wsplit);
    __nv_bfloat16* w = (__nv_bfloat16*)wp;
    const size_t WSZ = 512u * 512u;
    __nv_bfloat16* wqh = w + 0 * 2 * WSZ; __nv_bfloat16* wql = wqh + WSZ;
    __nv_bfloat16* wkh = w + 1 * 2 * WSZ; __nv_bfloat16* wkl = wkh + WSZ;
    __nv_bfloat16* wvh = w + 2 * 2 * WSZ; __nv_bfloat16* wvl = wvh + WSZ;
    __nv_bfloat16* f1h = w + 3 * 2 * WSZ; __nv_bfloat16* f1l = f1h + WSZ;
    __nv_bfloat16* f2h = w + 4 * 2 * WSZ; __nv_bfloat16* f2l = f2h + WSZ;

    cudaFuncSetAttribute(gemm_hl<true, false>,  cudaFuncAttributeMaxDynamicSharedMemorySize, GEMM_SMEM);
    cudaFuncSetAttribute(gemm_hl<false, false>, cudaFuncAttributeMaxDynamicSharedMemorySize, GEMM_SMEM);
    cudaFuncSetAttribute(gemm_hl<true, true>,   cudaFuncAttributeMaxDynamicSharedMemorySize, GEMM_SMEM);

    const dim3 blk(256);

    // weight prep (one launch, 5 weights)
    prep_weight5<<<dim3(16, 16, 5), dim3(32, 8)>>>(w_q, w_k, w_v, ffn_w1, ffn_w2, w);

    // activation hi/lo splits for the raw inputs
    f32_to_hl<<<NQ  * DD / 1024, blk>>>((const float4*)query, (uint2*)qh, (uint2*)ql);
    f32_to_hl<<<NKV * DD / 1024, blk>>>((const float4*)key,   (uint2*)kh, (uint2*)kl);
    f32_to_hl<<<NKV * DD / 1024, blk>>>((const float4*)value, (uint2*)vh, (uint2*)vl);

    const dim3 grid_q(DD / 128, NQ / 128);   // 4 x 64
    const dim3 grid_kv(DD / 128, NKV / 128); // 4 x 256

    gemm_hl<true,  false><<<grid_q,  blk, GEMM_SMEM>>>(qh, ql, wqh, wql, b_q, g_q, nullptr, nullptr);
    gemm_hl<true,  false><<<grid_kv, blk, GEMM_SMEM>>>(kh, kl, wkh, wkl, b_k, g_k, nullptr, nullptr);
    gemm_hl<false, false><<<grid_kv, blk, GEMM_SMEM>>>(vh, vl, wvh, wvl, b_v, g_v, nullptr, nullptr);

    attn_ln_kernel<<<NQ, blk>>>(g_q, g_k, g_v, ln1_g, ln1_b, g_out1, o1h, o1l);

    gemm_hl<true,  true ><<<grid_q, blk, GEMM_SMEM>>>(o1h, o1l, f1h, f1l, ffn_b1, nullptr, hh, hl);
    gemm_hl<false, false><<<grid_q, blk, GEMM_SMEM>>>(hh, hl, f2h, f2l, ffn_b2, g_ffn, nullptr, nullptr);

    resid_ln_kernel<<<NQ, blk>>>(g_out1, g_ffn, ln2_g, ln2_b, out);
}

// round 5
// speedup vs baseline: 1.3333x; 1.3333x over previous
#include <cuda_runtime.h>
#include <cuda_bf16.h>
#include <cstdint>

// ---------------------------------------------------------------------------
// AttentionSampling: B=4, SQ=2048, SK=8192, D=H=512, F=4, fp32.
// GEMMs via mma.sync bf16 hi/lo 3-pass (HMMA issue-bound at rt~16/SMSP).
// Algebraic restructure: V projection commuted past downsampling (4x fewer
// V-GEMM rows); q.k dot fused into K-GEMM epilogue (k never stored).
// ---------------------------------------------------------------------------

#define DD 512
#define NQ  8192
#define NKV 32768
#define EPS 1e-5f

// fp32 scratch planes
#define F_Q   0
#define F_AO  (F_Q  + (size_t)NQ * DD)
#define F_O1  (F_AO + (size_t)NQ * DD)
#define F_FF  (F_O1 + (size_t)NQ * DD)
#define F_WP  (F_FF + (size_t)NQ * DD)          // w_part [NKV][16]
#define F_SW  (F_WP + (size_t)NKV * 16)         // sum-of-w [NQ]
#define F_TOT (F_SW + (size_t)NQ)
__device__ float g_scratch[F_TOT];

// bf16 hi/lo activation planes
#define B_QH  0
#define B_QL  (B_QH  + (size_t)NQ  * DD)
#define B_KH  (B_QL  + (size_t)NQ  * DD)
#define B_KL  (B_KH  + (size_t)NKV * DD)
#define B_VH  (B_KL  + (size_t)NKV * DD)        // downsampled value (NQ rows)
#define B_VL  (B_VH  + (size_t)NQ  * DD)
#define B_O1H (B_VL  + (size_t)NQ  * DD)
#define B_O1L (B_O1H + (size_t)NQ  * DD)
#define B_HH  (B_O1L + (size_t)NQ  * DD)
#define B_HL  (B_HH  + (size_t)NQ  * DD)
#define B_TOT (B_HL  + (size_t)NQ  * DD)
__device__ __nv_bfloat16 g_act[B_TOT];

// 5 weights x (hi,lo) x 512x512 bf16, stored [N][K] (transposed)
__device__ __nv_bfloat16 g_wsplit[5u * 2u * 512u * 512u];

// ---------------------------------------------------------------------------
// PTX helpers (base sm_100-legal)
// ---------------------------------------------------------------------------
__device__ __forceinline__ uint32_t smem_u32(const void* p) {
    uint32_t a;
    asm("{ .reg .u64 t; cvta.to.shared.u64 t, %1; cvt.u32.u64 %0, t; }"
        : "=r"(a) : "l"(p));
    return a;
}
__device__ __forceinline__ void ldsm_x4(uint32_t* r, uint32_t addr) {
    asm volatile("ldmatrix.sync.aligned.m8n8.x4.shared.b16 {%0,%1,%2,%3}, [%4];"
                 : "=r"(r[0]), "=r"(r[1]), "=r"(r[2]), "=r"(r[3]) : "r"(addr));
}
__device__ __forceinline__ void mma16816(float* c, const uint32_t* a, const uint32_t* b) {
    asm volatile(
        "mma.sync.aligned.m16n8k16.row.col.f32.bf16.bf16.f32 "
        "{%0,%1,%2,%3}, {%4,%5,%6,%7}, {%8,%9}, {%0,%1,%2,%3};"
        : "+f"(c[0]), "+f"(c[1]), "+f"(c[2]), "+f"(c[3])
        : "r"(a[0]), "r"(a[1]), "r"(a[2]), "r"(a[3]), "r"(b[0]), "r"(b[1]));
}
__device__ __forceinline__ void cp16(uint32_t saddr, const void* g) {
    asm volatile("cp.async.cg.shared.global [%0], [%1], 16;"
                 :: "r"(saddr), "l"(g) : "memory");
}
__device__ __forceinline__ void cp_commit() {
    asm volatile("cp.async.commit_group;" ::: "memory");
}
__device__ __forceinline__ void split_bf16(float x, __nv_bfloat16& h, __nv_bfloat16& l) {
    h = __float2bfloat16(x);
    l = __float2bfloat16(x - __bfloat162float(h));
}

// ---------------------------------------------------------------------------
// Batched weight prep: W[k][n] fp32 -> Th[n][k], Tl[n][k] bf16 (5 weights)
// ---------------------------------------------------------------------------
__global__ void prep_weight5(
    const float* w0, const float* w1, const float* w2, const float* w3, const float* w4,
    __nv_bfloat16* base)
{
    const float* Ws[5] = {w0, w1, w2, w3, w4};
    const size_t WSZ = 512u * 512u;
    const float* W = Ws[blockIdx.z];
    __nv_bfloat16* Th = base + (size_t)blockIdx.z * 2u * WSZ;
    __nv_bfloat16* Tl = Th + WSZ;

    __shared__ float t[32][33];
    const int bx = blockIdx.x * 32, by = blockIdx.y * 32;
    const int tx = threadIdx.x, ty = threadIdx.y; // 32 x 8
#pragma unroll
    for (int i = 0; i < 32; i += 8)
        t[ty + i][tx] = W[(size_t)(by + ty + i) * DD + bx + tx];
    __syncthreads();
#pragma unroll
    for (int i = 0; i < 32; i += 8) {
        float x = t[tx][ty + i];
        __nv_bfloat16 h, l;
        split_bf16(x, h, l);
        size_t o = (size_t)(bx + ty + i) * DD + by + tx;
        Th[o] = h;
        Tl[o] = l;
    }
}

// ---------------------------------------------------------------------------
// fp32 -> bf16 hi/lo split (vectorized)
// ---------------------------------------------------------------------------
__global__ void __launch_bounds__(256) f32_to_hl(
    const float4* __restrict__ src, uint2* __restrict__ dh, uint2* __restrict__ dl)
{
    const int i = blockIdx.x * 256 + threadIdx.x;
    float4 x = src[i];
    __nv_bfloat16 hx, hy, hz, hw, lx, ly, lz, lw;
    split_bf16(x.x, hx, lx); split_bf16(x.y, hy, ly);
    split_bf16(x.z, hz, lz); split_bf16(x.w, hw, lw);
    __nv_bfloat162 h01, h23, l01, l23;
    h01.x = hx; h01.y = hy; h23.x = hz; h23.y = hw;
    l01.x = lx; l01.y = ly; l23.x = lz; l23.y = lw;
    uint2 hv, lv;
    hv.x = *(uint32_t*)&h01; hv.y = *(uint32_t*)&h23;
    lv.x = *(uint32_t*)&l01; lv.y = *(uint32_t*)&l23;
    dh[i] = hv;
    dl[i] = lv;
}

// ---------------------------------------------------------------------------
// HMMA GEMM: act(A[M,512] @ W[512,512] + bias)
// BM=128, BN=128, BK=32, 256 thr (8 warps 2m x 4n; warp tile 64x32).
// 4-stage cp.async pipeline; rows padded to 80B for conflict-free ldmatrix.
// DOTQ: instead of storing C, relu rows are dotted with q rows (kv row r ->
//       q row r>>2) and per-(CTA,n-warp) partials written to wpart[row][16].
// ---------------------------------------------------------------------------
#define BKC 32
#define NCH (DD / BKC)          // 16
#define RSTRB 80
#define PLANE (128 * RSTRB)
#define SG_AH 0
#define SG_AL (1 * PLANE)
#define SG_BH (2 * PLANE)
#define SG_BL (3 * PLANE)
#define SG_SZ (4 * PLANE)       // 40960
#define STAGES 4
#define GEMM_SMEM (STAGES * SG_SZ) // 163840

template <bool RELU, bool OUT_HL, bool DOTQ, bool HASBIAS>
__global__ void __launch_bounds__(256, 1) gemm_hl(
    const __nv_bfloat16* __restrict__ Ah, const __nv_bfloat16* __restrict__ Al,
    const __nv_bfloat16* __restrict__ Bh, const __nv_bfloat16* __restrict__ Bl,
    const float* __restrict__ bias, float* __restrict__ C,
    __nv_bfloat16* __restrict__ Ch, __nv_bfloat16* __restrict__ Cl,
    const float* __restrict__ qdot, float* __restrict__ wpart)
{
    extern __shared__ char sm[];
    const uint32_t sb = smem_u32(sm);

    const int tid = threadIdx.x;
    const int lane = tid & 31, wid = tid >> 5;
    const int wm = (wid & 1) * 64;
    const int wn = (wid >> 1) * 32;
    const int bm = blockIdx.y * 128;
    const int bn = blockIdx.x * 128;

    float acc[4][4][4];
#pragma unroll
    for (int i = 0; i < 4; i++)
#pragma unroll
        for (int j = 0; j < 4; j++)
#pragma unroll
            for (int t = 0; t < 4; t++) acc[i][j][t] = 0.f;

    const int row0 = tid >> 2, seg0 = tid & 3;
    const int row1 = (tid + 256) >> 2, seg1 = tid & 3;

    auto load_stage = [&](int c, int buf) {
        const uint32_t st = sb + buf * SG_SZ;
        const int kc = c * BKC;
        {
            uint32_t so = (uint32_t)row0 * RSTRB + seg0 * 16;
            size_t ga = (size_t)(bm + row0) * DD + kc + seg0 * 8;
            size_t gb = (size_t)(bn + row0) * DD + kc + seg0 * 8;
            cp16(st + SG_AH + so, Ah + ga);
            cp16(st + SG_AL + so, Al + ga);
            cp16(st + SG_BH + so, Bh + gb);
            cp16(st + SG_BL + so, Bl + gb);
        }
        {
            uint32_t so = (uint32_t)row1 * RSTRB + seg1 * 16;
            size_t ga = (size_t)(bm + row1) * DD + kc + seg1 * 8;
            size_t gb = (size_t)(bn + row1) * DD + kc + seg1 * 8;
            cp16(st + SG_AH + so, Ah + ga);
            cp16(st + SG_AL + so, Al + ga);
            cp16(st + SG_BH + so, Bh + gb);
            cp16(st + SG_BL + so, Bl + gb);
        }
        cp_commit();
    };

    const int a_r = wm + (lane & 15);
    const int a_cb = (lane >> 4) * 16;
    const int b_r = wn + ((lane >> 4) << 3) + (lane & 7);
    const int b_cb = ((lane >> 3) & 1) * 16;

    uint32_t ah[2][4][4], al[2][4][4], bh[2][2][4], bl[2][2][4];

#define LOADFRAG(ST, KS, DST) do {                                          \
        const uint32_t kb = (KS) * 32;                                      \
        _Pragma("unroll")                                                   \
        for (int i = 0; i < 4; i++) {                                       \
            uint32_t off = (uint32_t)(a_r + i * 16) * RSTRB + kb + a_cb;    \
            ldsm_x4(ah[DST][i], (ST) + SG_AH + off);                        \
            ldsm_x4(al[DST][i], (ST) + SG_AL + off);                        \
        }                                                                   \
        _Pragma("unroll")                                                   \
        for (int jp = 0; jp < 2; jp++) {                                    \
            uint32_t off = (uint32_t)(b_r + jp * 16) * RSTRB + kb + b_cb;   \
            ldsm_x4(bh[DST][jp], (ST) + SG_BH + off);                       \
            ldsm_x4(bl[DST][jp], (ST) + SG_BL + off);                       \
        }                                                                   \
    } while (0)

    auto compute = [&](int buf) {
        const uint32_t st = sb + buf * SG_SZ;
        LOADFRAG(st, 0, 0);
#pragma unroll
        for (int ks = 0; ks < 2; ks++) {
            if (ks == 0) LOADFRAG(st, 1, 1);
#pragma unroll
            for (int i = 0; i < 4; i++)
#pragma unroll
                for (int j = 0; j < 4; j++)
                    mma16816(acc[i][j], ah[ks][i], &bh[ks][j >> 1][(j & 1) * 2]);
#pragma unroll
            for (int i = 0; i < 4; i++)
#pragma unroll
                for (int j = 0; j < 4; j++)
                    mma16816(acc[i][j], ah[ks][i], &bl[ks][j >> 1][(j & 1) * 2]);
#pragma unroll
            for (int i = 0; i < 4; i++)
#pragma unroll
                for (int j = 0; j < 4; j++)
                    mma16816(acc[i][j], al[ks][i], &bh[ks][j >> 1][(j & 1) * 2]);
        }
    };

    load_stage(0, 0);
    load_stage(1, 1);
    load_stage(2, 2);

#pragma unroll 1
    for (int c = 0; c < NCH; c++) {
        asm volatile("cp.async.wait_group 2;" ::: "memory");
        __syncthreads();
        if (c + 3 < NCH) load_stage(c + 3, (c + 3) & 3);
        compute(c & 3);
    }

    // ---------------- epilogue ----------------
    const int crow = lane >> 2, ccol = (lane & 3) * 2;

    if (DOTQ) {
        // k = relu(acc + bias); accumulate k . q per kv-row; q row = kv row >> 2
        float dotr[4][2];
#pragma unroll
        for (int i = 0; i < 4; i++) { dotr[i][0] = 0.f; dotr[i][1] = 0.f; }
#pragma unroll
        for (int i = 0; i < 4; i++) {
            const int r0 = bm + wm + i * 16 + crow;
            const float* q0p = qdot + (size_t)(r0 >> 2) * DD;
            const float* q1p = qdot + (size_t)((r0 + 8) >> 2) * DD;
#pragma unroll
            for (int j = 0; j < 4; j++) {
                const int col = bn + wn + j * 8 + ccol;
                float bx = 0.f, by = 0.f;
                if (HASBIAS) {
                    float2 bv = *(const float2*)(bias + col);
                    bx = bv.x; by = bv.y;
                }
                float k00 = fmaxf(acc[i][j][0] + bx, 0.f);
                float k01 = fmaxf(acc[i][j][1] + by, 0.f);
                float k10 = fmaxf(acc[i][j][2] + bx, 0.f);
                float k11 = fmaxf(acc[i][j][3] + by, 0.f);
                float2 q0 = *(const float2*)(q0p + col);
                float2 q1 = *(const float2*)(q1p + col);
                dotr[i][0] += k00 * q0.x + k01 * q0.y;
                dotr[i][1] += k10 * q1.x + k11 * q1.y;
            }
        }
        // quad-reduce (lanes crow*4+{0..3} share a row) and store partial
#pragma unroll
        for (int i = 0; i < 4; i++)
#pragma unroll
            for (int p = 0; p < 2; p++) {
                float v = dotr[i][p];
                v += __shfl_xor_sync(0xffffffffu, v, 1);
                v += __shfl_xor_sync(0xffffffffu, v, 2);
                if ((lane & 3) == 0) {
                    const int row = bm + wm + i * 16 + crow + p * 8;
                    wpart[(size_t)row * 16 + blockIdx.x * 4 + (wid >> 1)] = v;
                }
            }
        return;
    }

#pragma unroll
    for (int i = 0; i < 4; i++) {
        const int r0 = bm + wm + i * 16 + crow;
#pragma unroll
        for (int j = 0; j < 4; j++) {
            const int col = bn + wn + j * 8 + ccol;
            float bx = 0.f, by = 0.f;
            if (HASBIAS) {
                float2 bv = *(const float2*)(bias + col);
                bx = bv.x; by = bv.y;
            }
            float2 o0, o1;
            o0.x = acc[i][j][0] + bx; o0.y = acc[i][j][1] + by;
            o1.x = acc[i][j][2] + bx; o1.y = acc[i][j][3] + by;
            if (RELU) {
                o0.x = fmaxf(o0.x, 0.f); o0.y = fmaxf(o0.y, 0.f);
                o1.x = fmaxf(o1.x, 0.f); o1.y = fmaxf(o1.y, 0.f);
            }
            if (OUT_HL) {
                __nv_bfloat162 h2, l2;
                split_bf16(o0.x, h2.x, l2.x); split_bf16(o0.y, h2.y, l2.y);
                *(__nv_bfloat162*)(Ch + (size_t)r0 * DD + col) = h2;
                *(__nv_bfloat162*)(Cl + (size_t)r0 * DD + col) = l2;
                split_bf16(o1.x, h2.x, l2.x); split_bf16(o1.y, h2.y, l2.y);
                *(__nv_bfloat162*)(Ch + (size_t)(r0 + 8) * DD + col) = h2;
                *(__nv_bfloat162*)(Cl + (size_t)(r0 + 8) * DD + col) = l2;
            } else {
                *(float2*)(C + (size_t)r0 * DD + col) = o0;
                *(float2*)(C + (size_t)(r0 + 8) * DD + col) = o1;
            }
        }
    }
}

// ---------------------------------------------------------------------------
// Downsample: vds[s,:] = sum_f w[4s+f] * value[4s+f,:]; also sw[s] = sum_f w.
// w[r] = sum of 16 partials in wpart[r][0..15]. Emits vds as bf16 hi/lo.
// ---------------------------------------------------------------------------
__global__ void __launch_bounds__(256) wds_kernel(
    const float* __restrict__ wpart, const float* __restrict__ value,
    __nv_bfloat16* __restrict__ vh, __nv_bfloat16* __restrict__ vl,
    float* __restrict__ sw)
{
    const int s = blockIdx.x;           // global q row
    const int tid = threadIdx.x;
    __shared__ float wp[64];
    __shared__ float wf[4];
    if (tid < 64) wp[tid] = wpart[(size_t)s * 64 + tid];
    __syncthreads();
    if (tid < 4) {
        float a = 0.f;
#pragma unroll
        for (int p = 0; p < 16; p++) a += wp[tid * 16 + p];
        wf[tid] = a;
    }
    __syncthreads();
    const float w0 = wf[0], w1 = wf[1], w2 = wf[2], w3 = wf[3];
    if (tid == 0) sw[s] = w0 + w1 + w2 + w3;

    const float* vr = value + (size_t)s * 4 * DD;
    const size_t o = (size_t)s * DD;
#pragma unroll
    for (int u = 0; u < 2; u++) {
        const int d = tid + u * 256;
        float x = w0 * vr[d] + w1 * vr[DD + d] + w2 * vr[2 * DD + d] + w3 * vr[3 * DD + d];
        __nv_bfloat16 h, l;
        split_bf16(x, h, l);
        vh[o + d] = h;
        vl[o + d] = l;
    }
}

// ---------------------------------------------------------------------------
// warp reduction
// ---------------------------------------------------------------------------
__device__ __forceinline__ float warp_sum(float x) {
#pragma unroll
    for (int o = 16; o > 0; o >>= 1) x += __shfl_xor_sync(0xffffffffu, x, o);
    return x;
}

// ---------------------------------------------------------------------------
// LN1: r = q + ao + sw*b_v; out1 = LN(r) (fp32 + bf16 hi/lo)
// ---------------------------------------------------------------------------
__global__ void __launch_bounds__(256) attn_ln_kernel(
    const float* __restrict__ q, const float* __restrict__ ao,
    const float* __restrict__ sw, const float* __restrict__ bv,
    const float* __restrict__ gamma, const float* __restrict__ beta,
    float* __restrict__ out,
    __nv_bfloat16* __restrict__ outh, __nv_bfloat16* __restrict__ outl)
{
    const int row = blockIdx.x;
    const int tid = threadIdx.x;
    const int lane = tid & 31, wid = tid >> 5;
    const size_t off = (size_t)row * DD;
    const float swv = sw[row];

    float r0 = q[off + tid]       + ao[off + tid]       + swv * bv[tid];
    float r1 = q[off + tid + 256] + ao[off + tid + 256] + swv * bv[tid + 256];

    float s = warp_sum(r0 + r1);
    float ss = warp_sum(r0 * r0 + r1 * r1);
    __shared__ float rs[8], rss[8];
    if (lane == 0) { rs[wid] = s; rss[wid] = ss; }
    __syncthreads();
    __shared__ float mv[2];
    if (tid == 0) {
        float S = 0.f, SS = 0.f;
#pragma unroll
        for (int i = 0; i < 8; i++) { S += rs[i]; SS += rss[i]; }
        float mean = S * (1.f / 512.f);
        float var = SS * (1.f / 512.f) - mean * mean;
        mv[0] = mean; mv[1] = rsqrtf(var + EPS);
    }
    __syncthreads();
    const float mean = mv[0], inv = mv[1];
    float y0 = (r0 - mean) * inv * gamma[tid]       + beta[tid];
    float y1 = (r1 - mean) * inv * gamma[tid + 256] + beta[tid + 256];
    out[off + tid] = y0;
    out[off + tid + 256] = y1;
    __nv_bfloat16 h, l;
    split_bf16(y0, h, l); outh[off + tid] = h;       outl[off + tid] = l;
    split_bf16(y1, h, l); outh[off + tid + 256] = h; outl[off + tid + 256] = l;
}

// ---------------------------------------------------------------------------
// Fused residual + LayerNorm2 -> output
// ---------------------------------------------------------------------------
__global__ void __launch_bounds__(256) resid_ln_kernel(
    const float* __restrict__ a, const float* __restrict__ f,
    const float* __restrict__ gamma, const float* __restrict__ beta,
    float* __restrict__ out)
{
    const int row = blockIdx.x;
    const int tid = threadIdx.x;
    const int lane = tid & 31, wid = tid >> 5;
    const size_t off = (size_t)row * DD;

    float r0 = a[off + tid]       + f[off + tid];
    float r1 = a[off + tid + 256] + f[off + tid + 256];

    float s = warp_sum(r0 + r1);
    float ss = warp_sum(r0 * r0 + r1 * r1);
    __shared__ float rs[8], rss[8];
    if (lane == 0) { rs[wid] = s; rss[wid] = ss; }
    __syncthreads();
    __shared__ float mv[2];
    if (tid == 0) {
        float S = 0.f, SS = 0.f;
#pragma unroll
        for (int i = 0; i < 8; i++) { S += rs[i]; SS += rss[i]; }
        float mean = S * (1.f / 512.f);
        float var = SS * (1.f / 512.f) - mean * mean;
        mv[0] = mean; mv[1] = rsqrtf(var + EPS);
    }
    __syncthreads();
    const float mean = mv[0], inv = mv[1];
    out[off + tid]       = (r0 - mean) * inv * gamma[tid]       + beta[tid];
    out[off + tid + 256] = (r1 - mean) * inv * gamma[tid + 256] + beta[tid + 256];
}

// ---------------------------------------------------------------------------
// Launch
// ---------------------------------------------------------------------------
extern "C" void kernel_launch(void* const* d_in, const int* in_sizes, int n_in,
                              void* d_out, int out_size)
{
    const float* query  = (const float*)d_in[0];
    const float* key    = (const float*)d_in[1];
    const float* value  = (const float*)d_in[2];
    const float* w_q    = (const float*)d_in[3];
    const float* b_q    = (const float*)d_in[4];
    const float* w_k    = (const float*)d_in[5];
    const float* b_k    = (const float*)d_in[6];
    const float* w_v    = (const float*)d_in[7];
    const float* b_v    = (const float*)d_in[8];
    const float* ln1_g  = (const float*)d_in[9];
    const float* ln1_b  = (const float*)d_in[10];
    const float* ln2_g  = (const float*)d_in[11];
    const float* ln2_b  = (const float*)d_in[12];
    const float* ffn_w1 = (const float*)d_in[13];
    const float* ffn_b1 = (const float*)d_in[14];
    const float* ffn_w2 = (const float*)d_in[15];
    const float* ffn_b2 = (const float*)d_in[16];
    float* out = (float*)d_out;

    void* sp = nullptr;
    cudaGetSymbolAddress(&sp, g_scratch);
    float* s = (float*)sp;
    float* g_q    = s + F_Q;
    float* g_ao   = s + F_AO;
    float* g_out1 = s + F_O1;
    float* g_ffn  = s + F_FF;
    float* g_wp   = s + F_WP;
    float* g_sw   = s + F_SW;

    void* ap = nullptr;
    cudaGetSymbolAddress(&ap, g_act);
    __nv_bfloat16* a = (__nv_bfloat16*)ap;
    __nv_bfloat16* qh  = a + B_QH;  __nv_bfloat16* ql  = a + B_QL;
    __nv_bfloat16* kh  = a + B_KH;  __nv_bfloat16* kl  = a + B_KL;
    __nv_bfloat16* vh  = a + B_VH;  __nv_bfloat16* vl  = a + B_VL;
    __nv_bfloat16* o1h = a + B_O1H; __nv_bfloat16* o1l = a + B_O1L;
    __nv_bfloat16* hh  = a + B_HH;  __nv_bfloat16* hl  = a + B_HL;

    void* wp = nullptr;
    cudaGetSymbolAddress(&wp, g_wsplit);
    __nv_bfloat16* w = (__nv_bfloat16*)wp;
    const size_t WSZ = 512u * 512u;
    __nv_bfloat16* wqh = w + 0 * 2 * WSZ; __nv_bfloat16* wql = wqh + WSZ;
    __nv_bfloat16* wkh = w + 1 * 2 * WSZ; __nv_bfloat16* wkl = wkh + WSZ;
    __nv_bfloat16* wvh = w + 2 * 2 * WSZ; __nv_bfloat16* wvl = wvh + WSZ;
    __nv_bfloat16* f1h = w + 3 * 2 * WSZ; __nv_bfloat16* f1l = f1h + WSZ;
    __nv_bfloat16* f2h = w + 4 * 2 * WSZ; __nv_bfloat16* f2l = f2h + WSZ;

    cudaFuncSetAttribute((const void*)gemm_hl<true,  false, false, true >, cudaFuncAttributeMaxDynamicSharedMemorySize, GEMM_SMEM);
    cudaFuncSetAttribute((const void*)gemm_hl<true,  false, true,  true >, cudaFuncAttributeMaxDynamicSharedMemorySize, GEMM_SMEM);
    cudaFuncSetAttribute((const void*)gemm_hl<false, false, false, false>, cudaFuncAttributeMaxDynamicSharedMemorySize, GEMM_SMEM);
    cudaFuncSetAttribute((const void*)gemm_hl<true,  true,  false, true >, cudaFuncAttributeMaxDynamicSharedMemorySize, GEMM_SMEM);
    cudaFuncSetAttribute((const void*)gemm_hl<false, false, false, true >, cudaFuncAttributeMaxDynamicSharedMemorySize, GEMM_SMEM);

    const dim3 blk(256);

    // prep: weights + input activation splits (value needs no split)
    prep_weight5<<<dim3(16, 16, 5), dim3(32, 8)>>>(w_q, w_k, w_v, ffn_w1, ffn_w2, w);
    f32_to_hl<<<NQ  * DD / 1024, blk>>>((const float4*)query, (uint2*)qh, (uint2*)ql);
    f32_to_hl<<<NKV * DD / 1024, blk>>>((const float4*)key,   (uint2*)kh, (uint2*)kl);

    const dim3 grid_q(DD / 128, NQ / 128);   // 4 x 64
    const dim3 grid_kv(DD / 128, NKV / 128); // 4 x 256

    // Q projection (fp32 out; consumed by residual and the fused q.k dot)
    gemm_hl<true, false, false, true><<<grid_q, blk, GEMM_SMEM>>>(
        qh, ql, wqh, wql, b_q, g_q, nullptr, nullptr, nullptr, nullptr);

    // K projection with fused q.k dot -> w partials (k never stored)
    gemm_hl<true, false, true, true><<<grid_kv, blk, GEMM_SMEM>>>(
        kh, kl, wkh, wkl, b_k, nullptr, nullptr, nullptr, g_q, g_wp);

    // downsample raw value by w -> vds (bf16 hi/lo), and sw = sum_f w
    wds_kernel<<<NQ, blk>>>(g_wp, value, vh, vl, g_sw);

    // V projection on downsampled rows (no bias here; sw*b_v added in LN1)
    gemm_hl<false, false, false, false><<<grid_q, blk, GEMM_SMEM>>>(
        vh, vl, wvh, wvl, nullptr, g_ao, nullptr, nullptr, nullptr, nullptr);

    // LN1 (adds q + ao + sw*b_v)
    attn_ln_kernel<<<NQ, blk>>>(g_q, g_ao, g_sw, b_v, ln1_g, ln1_b, g_out1, o1h, o1l);

    // FFN
    gemm_hl<true, true, false, true><<<grid_q, blk, GEMM_SMEM>>>(
        o1h, o1l, f1h, f1l, ffn_b1, nullptr, hh, hl, nullptr, nullptr);
    gemm_hl<false, false, false, true><<<grid_q, blk, GEMM_SMEM>>>(
        hh, hl, f2h, f2l, ffn_b2, g_ffn, nullptr, nullptr, nullptr, nullptr);

    resid_ln_kernel<<<NQ, blk>>>(g_out1, g_ffn, ln2_g, ln2_b, out);
}

// round 6
// speedup vs baseline: 1.4558x; 1.0918x over previous
#include <cuda_runtime.h>
#include <cuda_bf16.h>
#include <cstdint>

// ---------------------------------------------------------------------------
// AttentionSampling: B=4, SQ=2048, SK=8192, D=H=512, F=4, fp32.
// GEMMs via mma.sync bf16 hi/lo 3-pass. Round 6: 2-stage pipeline (80KB smem)
// + <=128 regs so 2 CTAs/SM co-reside (was 1 -> tensor pipe 43% idle-bound).
// ---------------------------------------------------------------------------

#define DD 512
#define NQ  8192
#define NKV 32768
#define EPS 1e-5f

// fp32 scratch planes
#define F_Q   0
#define F_AO  (F_Q  + (size_t)NQ * DD)
#define F_O1  (F_AO + (size_t)NQ * DD)
#define F_FF  (F_O1 + (size_t)NQ * DD)
#define F_WP  (F_FF + (size_t)NQ * DD)          // w_part [NKV][16]
#define F_SW  (F_WP + (size_t)NKV * 16)         // sum-of-w [NQ]
#define F_TOT (F_SW + (size_t)NQ)
__device__ float g_scratch[F_TOT];

// bf16 hi/lo activation planes
#define B_QH  0
#define B_QL  (B_QH  + (size_t)NQ  * DD)
#define B_KH  (B_QL  + (size_t)NQ  * DD)
#define B_KL  (B_KH  + (size_t)NKV * DD)
#define B_VH  (B_KL  + (size_t)NKV * DD)        // downsampled value (NQ rows)
#define B_VL  (B_VH  + (size_t)NQ  * DD)
#define B_O1H (B_VL  + (size_t)NQ  * DD)
#define B_O1L (B_O1H + (size_t)NQ  * DD)
#define B_HH  (B_O1L + (size_t)NQ  * DD)
#define B_HL  (B_HH  + (size_t)NQ  * DD)
#define B_TOT (B_HL  + (size_t)NQ  * DD)
__device__ __nv_bfloat16 g_act[B_TOT];

// 5 weights x (hi,lo) x 512x512 bf16, stored [N][K] (transposed)
__device__ __nv_bfloat16 g_wsplit[5u * 2u * 512u * 512u];

// ---------------------------------------------------------------------------
// PTX helpers (base sm_100-legal)
// ---------------------------------------------------------------------------
__device__ __forceinline__ uint32_t smem_u32(const void* p) {
    uint32_t a;
    asm("{ .reg .u64 t; cvta.to.shared.u64 t, %1; cvt.u32.u64 %0, t; }"
        : "=r"(a) : "l"(p));
    return a;
}
__device__ __forceinline__ void ldsm_x4(uint32_t* r, uint32_t addr) {
    asm volatile("ldmatrix.sync.aligned.m8n8.x4.shared.b16 {%0,%1,%2,%3}, [%4];"
                 : "=r"(r[0]), "=r"(r[1]), "=r"(r[2]), "=r"(r[3]) : "r"(addr));
}
__device__ __forceinline__ void mma16816(float* c, const uint32_t* a, const uint32_t* b) {
    asm volatile(
        "mma.sync.aligned.m16n8k16.row.col.f32.bf16.bf16.f32 "
        "{%0,%1,%2,%3}, {%4,%5,%6,%7}, {%8,%9}, {%0,%1,%2,%3};"
        : "+f"(c[0]), "+f"(c[1]), "+f"(c[2]), "+f"(c[3])
        : "r"(a[0]), "r"(a[1]), "r"(a[2]), "r"(a[3]), "r"(b[0]), "r"(b[1]));
}
__device__ __forceinline__ void cp16(uint32_t saddr, const void* g) {
    asm volatile("cp.async.cg.shared.global [%0], [%1], 16;"
                 :: "r"(saddr), "l"(g) : "memory");
}
__device__ __forceinline__ void cp_commit() {
    asm volatile("cp.async.commit_group;" ::: "memory");
}
__device__ __forceinline__ void split_bf16(float x, __nv_bfloat16& h, __nv_bfloat16& l) {
    h = __float2bfloat16(x);
    l = __float2bfloat16(x - __bfloat162float(h));
}

// ---------------------------------------------------------------------------
// Batched weight prep: W[k][n] fp32 -> Th[n][k], Tl[n][k] bf16 (5 weights)
// ---------------------------------------------------------------------------
__global__ void prep_weight5(
    const float* w0, const float* w1, const float* w2, const float* w3, const float* w4,
    __nv_bfloat16* base)
{
    const float* Ws[5] = {w0, w1, w2, w3, w4};
    const size_t WSZ = 512u * 512u;
    const float* W = Ws[blockIdx.z];
    __nv_bfloat16* Th = base + (size_t)blockIdx.z * 2u * WSZ;
    __nv_bfloat16* Tl = Th + WSZ;

    __shared__ float t[32][33];
    const int bx = blockIdx.x * 32, by = blockIdx.y * 32;
    const int tx = threadIdx.x, ty = threadIdx.y; // 32 x 8
#pragma unroll
    for (int i = 0; i < 32; i += 8)
        t[ty + i][tx] = W[(size_t)(by + ty + i) * DD + bx + tx];
    __syncthreads();
#pragma unroll
    for (int i = 0; i < 32; i += 8) {
        float x = t[tx][ty + i];
        __nv_bfloat16 h, l;
        split_bf16(x, h, l);
        size_t o = (size_t)(bx + ty + i) * DD + by + tx;
        Th[o] = h;
        Tl[o] = l;
    }
}

// ---------------------------------------------------------------------------
// fp32 -> bf16 hi/lo split (vectorized)
// ---------------------------------------------------------------------------
__global__ void __launch_bounds__(256) f32_to_hl(
    const float4* __restrict__ src, uint2* __restrict__ dh, uint2* __restrict__ dl)
{
    const int i = blockIdx.x * 256 + threadIdx.x;
    float4 x = src[i];
    __nv_bfloat16 hx, hy, hz, hw, lx, ly, lz, lw;
    split_bf16(x.x, hx, lx); split_bf16(x.y, hy, ly);
    split_bf16(x.z, hz, lz); split_bf16(x.w, hw, lw);
    __nv_bfloat162 h01, h23, l01, l23;
    h01.x = hx; h01.y = hy; h23.x = hz; h23.y = hw;
    l01.x = lx; l01.y = ly; l23.x = lz; l23.y = lw;
    uint2 hv, lv;
    hv.x = *(uint32_t*)&h01; hv.y = *(uint32_t*)&h23;
    lv.x = *(uint32_t*)&l01; lv.y = *(uint32_t*)&l23;
    dh[i] = hv;
    dl[i] = lv;
}

// ---------------------------------------------------------------------------
// HMMA GEMM: act(A[M,512] @ W[512,512] + bias)
// BM=128, BN=128, BK=32, 256 thr (8 warps 2m x 4n; warp tile 64x32).
// 2-stage cp.async pipeline (80KB) + launch_bounds(256,2) -> 2 CTAs/SM.
// DOTQ: k rows dotted with q rows instead of stored (w partials out).
// ---------------------------------------------------------------------------
#define BKC 32
#define NCH (DD / BKC)          // 16
#define RSTRB 80
#define PLANE (128 * RSTRB)
#define SG_AH 0
#define SG_AL (1 * PLANE)
#define SG_BH (2 * PLANE)
#define SG_BL (3 * PLANE)
#define SG_SZ (4 * PLANE)       // 40960
#define STAGES 2
#define GEMM_SMEM (STAGES * SG_SZ) // 81920

template <bool RELU, bool OUT_HL, bool DOTQ, bool HASBIAS>
__global__ void __launch_bounds__(256, 2) gemm_hl(
    const __nv_bfloat16* __restrict__ Ah, const __nv_bfloat16* __restrict__ Al,
    const __nv_bfloat16* __restrict__ Bh, const __nv_bfloat16* __restrict__ Bl,
    const float* __restrict__ bias, float* __restrict__ C,
    __nv_bfloat16* __restrict__ Ch, __nv_bfloat16* __restrict__ Cl,
    const float* __restrict__ qdot, float* __restrict__ wpart)
{
    extern __shared__ char sm[];
    const uint32_t sb = smem_u32(sm);

    const int tid = threadIdx.x;
    const int lane = tid & 31, wid = tid >> 5;
    const int wm = (wid & 1) * 64;
    const int wn = (wid >> 1) * 32;
    const int bm = blockIdx.y * 128;
    const int bn = blockIdx.x * 128;

    float acc[4][4][4];
#pragma unroll
    for (int i = 0; i < 4; i++)
#pragma unroll
        for (int j = 0; j < 4; j++)
#pragma unroll
            for (int t = 0; t < 4; t++) acc[i][j][t] = 0.f;

    const int row0 = tid >> 2, seg0 = tid & 3;
    const int row1 = (tid + 256) >> 2, seg1 = tid & 3;

    auto load_stage = [&](int c, int buf) {
        const uint32_t st = sb + buf * SG_SZ;
        const int kc = c * BKC;
        {
            uint32_t so = (uint32_t)row0 * RSTRB + seg0 * 16;
            size_t ga = (size_t)(bm + row0) * DD + kc + seg0 * 8;
            size_t gb = (size_t)(bn + row0) * DD + kc + seg0 * 8;
            cp16(st + SG_AH + so, Ah + ga);
            cp16(st + SG_AL + so, Al + ga);
            cp16(st + SG_BH + so, Bh + gb);
            cp16(st + SG_BL + so, Bl + gb);
        }
        {
            uint32_t so = (uint32_t)row1 * RSTRB + seg1 * 16;
            size_t ga = (size_t)(bm + row1) * DD + kc + seg1 * 8;
            size_t gb = (size_t)(bn + row1) * DD + kc + seg1 * 8;
            cp16(st + SG_AH + so, Ah + ga);
            cp16(st + SG_AL + so, Al + ga);
            cp16(st + SG_BH + so, Bh + gb);
            cp16(st + SG_BL + so, Bl + gb);
        }
        cp_commit();
    };

    const int a_r = wm + (lane & 15);
    const int a_cb = (lane >> 4) * 16;
    const int b_r = wn + ((lane >> 4) << 3) + (lane & 7);
    const int b_cb = ((lane >> 3) & 1) * 16;

    // single frag buffer (register budget: 2 CTAs/SM needs <=128 regs)
    auto compute = [&](int buf) {
        const uint32_t st = sb + buf * SG_SZ;
#pragma unroll
        for (int ks = 0; ks < 2; ks++) {
            uint32_t ah[4][4], al[4][4], bh[2][4], bl[2][4];
            const uint32_t kb = (uint32_t)(ks * 32);
#pragma unroll
            for (int i = 0; i < 4; i++) {
                uint32_t off = (uint32_t)(a_r + i * 16) * RSTRB + kb + a_cb;
                ldsm_x4(ah[i], st + SG_AH + off);
                ldsm_x4(al[i], st + SG_AL + off);
            }
#pragma unroll
            for (int jp = 0; jp < 2; jp++) {
                uint32_t off = (uint32_t)(b_r + jp * 16) * RSTRB + kb + b_cb;
                ldsm_x4(bh[jp], st + SG_BH + off);
                ldsm_x4(bl[jp], st + SG_BL + off);
            }
#pragma unroll
            for (int i = 0; i < 4; i++)
#pragma unroll
                for (int j = 0; j < 4; j++)
                    mma16816(acc[i][j], ah[i], &bh[j >> 1][(j & 1) * 2]);
#pragma unroll
            for (int i = 0; i < 4; i++)
#pragma unroll
                for (int j = 0; j < 4; j++)
                    mma16816(acc[i][j], ah[i], &bl[j >> 1][(j & 1) * 2]);
#pragma unroll
            for (int i = 0; i < 4; i++)
#pragma unroll
                for (int j = 0; j < 4; j++)
                    mma16816(acc[i][j], al[i], &bh[j >> 1][(j & 1) * 2]);
        }
    };

    // 2-stage pipeline
    load_stage(0, 0);
    load_stage(1, 1);

#pragma unroll 1
    for (int c = 0; c < NCH; c++) {
        if (c < NCH - 2)
            asm volatile("cp.async.wait_group 1;" ::: "memory");
        else
            asm volatile("cp.async.wait_group 0;" ::: "memory");
        __syncthreads();
        compute(c & 1);
        if (c + 2 < NCH) {
            __syncthreads();
            load_stage(c + 2, c & 1);
        }
    }

    // ---------------- epilogue ----------------
    const int crow = lane >> 2, ccol = (lane & 3) * 2;

    if (DOTQ) {
        float dotr[4][2];
#pragma unroll
        for (int i = 0; i < 4; i++) { dotr[i][0] = 0.f; dotr[i][1] = 0.f; }
#pragma unroll
        for (int i = 0; i < 4; i++) {
            const int r0 = bm + wm + i * 16 + crow;
            const float* q0p = qdot + (size_t)(r0 >> 2) * DD;
            const float* q1p = qdot + (size_t)((r0 + 8) >> 2) * DD;
#pragma unroll
            for (int j = 0; j < 4; j++) {
                const int col = bn + wn + j * 8 + ccol;
                float bx = 0.f, by = 0.f;
                if (HASBIAS) {
                    float2 bv = *(const float2*)(bias + col);
                    bx = bv.x; by = bv.y;
                }
                float k00 = fmaxf(acc[i][j][0] + bx, 0.f);
                float k01 = fmaxf(acc[i][j][1] + by, 0.f);
                float k10 = fmaxf(acc[i][j][2] + bx, 0.f);
                float k11 = fmaxf(acc[i][j][3] + by, 0.f);
                float2 q0 = *(const float2*)(q0p + col);
                float2 q1 = *(const float2*)(q1p + col);
                dotr[i][0] += k00 * q0.x + k01 * q0.y;
                dotr[i][1] += k10 * q1.x + k11 * q1.y;
            }
        }
#pragma unroll
        for (int i = 0; i < 4; i++)
#pragma unroll
            for (int p = 0; p < 2; p++) {
                float v = dotr[i][p];
                v += __shfl_xor_sync(0xffffffffu, v, 1);
                v += __shfl_xor_sync(0xffffffffu, v, 2);
                if ((lane & 3) == 0) {
                    const int row = bm + wm + i * 16 + crow + p * 8;
                    wpart[(size_t)row * 16 + blockIdx.x * 4 + (wid >> 1)] = v;
                }
            }
        return;
    }

#pragma unroll
    for (int i = 0; i < 4; i++) {
        const int r0 = bm + wm + i * 16 + crow;
#pragma unroll
        for (int j = 0; j < 4; j++) {
            const int col = bn + wn + j * 8 + ccol;
            float bx = 0.f, by = 0.f;
            if (HASBIAS) {
                float2 bv = *(const float2*)(bias + col);
                bx = bv.x; by = bv.y;
            }
            float2 o0, o1;
            o0.x = acc[i][j][0] + bx; o0.y = acc[i][j][1] + by;
            o1.x = acc[i][j][2] + bx; o1.y = acc[i][j][3] + by;
            if (RELU) {
                o0.x = fmaxf(o0.x, 0.f); o0.y = fmaxf(o0.y, 0.f);
                o1.x = fmaxf(o1.x, 0.f); o1.y = fmaxf(o1.y, 0.f);
            }
            if (OUT_HL) {
                __nv_bfloat162 h2, l2;
                split_bf16(o0.x, h2.x, l2.x); split_bf16(o0.y, h2.y, l2.y);
                *(__nv_bfloat162*)(Ch + (size_t)r0 * DD + col) = h2;
                *(__nv_bfloat162*)(Cl + (size_t)r0 * DD + col) = l2;
                split_bf16(o1.x, h2.x, l2.x); split_bf16(o1.y, h2.y, l2.y);
                *(__nv_bfloat162*)(Ch + (size_t)(r0 + 8) * DD + col) = h2;
                *(__nv_bfloat162*)(Cl + (size_t)(r0 + 8) * DD + col) = l2;
            } else {
                *(float2*)(C + (size_t)r0 * DD + col) = o0;
                *(float2*)(C + (size_t)(r0 + 8) * DD + col) = o1;
            }
        }
    }
}

// ---------------------------------------------------------------------------
// Downsample: vds[s,:] = sum_f w[4s+f] * value[4s+f,:]; sw[s] = sum_f w.
// ---------------------------------------------------------------------------
__global__ void __launch_bounds__(256) wds_kernel(
    const float* __restrict__ wpart, const float* __restrict__ value,
    __nv_bfloat16* __restrict__ vh, __nv_bfloat16* __restrict__ vl,
    float* __restrict__ sw)
{
    const int s = blockIdx.x;
    const int tid = threadIdx.x;
    __shared__ float wp[64];
    __shared__ float wf[4];
    if (tid < 64) wp[tid] = wpart[(size_t)s * 64 + tid];
    __syncthreads();
    if (tid < 4) {
        float a = 0.f;
#pragma unroll
        for (int p = 0; p < 16; p++) a += wp[tid * 16 + p];
        wf[tid] = a;
    }
    __syncthreads();
    const float w0 = wf[0], w1 = wf[1], w2 = wf[2], w3 = wf[3];
    if (tid == 0) sw[s] = w0 + w1 + w2 + w3;

    const float* vr = value + (size_t)s * 4 * DD;
    const size_t o = (size_t)s * DD;
#pragma unroll
    for (int u = 0; u < 2; u++) {
        const int d = tid + u * 256;
        float x = w0 * vr[d] + w1 * vr[DD + d] + w2 * vr[2 * DD + d] + w3 * vr[3 * DD + d];
        __nv_bfloat16 h, l;
        split_bf16(x, h, l);
        vh[o + d] = h;
        vl[o + d] = l;
    }
}

// ---------------------------------------------------------------------------
// warp reduction
// ---------------------------------------------------------------------------
__device__ __forceinline__ float warp_sum(float x) {
#pragma unroll
    for (int o = 16; o > 0; o >>= 1) x += __shfl_xor_sync(0xffffffffu, x, o);
    return x;
}

// ---------------------------------------------------------------------------
// LN1: r = q + ao + sw*b_v; out1 = LN(r) (fp32 + bf16 hi/lo)
// ---------------------------------------------------------------------------
__global__ void __launch_bounds__(256) attn_ln_kernel(
    const float* __restrict__ q, const float* __restrict__ ao,
    const float* __restrict__ sw, const float* __restrict__ bv,
    const float* __restrict__ gamma, const float* __restrict__ beta,
    float* __restrict__ out,
    __nv_bfloat16* __restrict__ outh, __nv_bfloat16* __restrict__ outl)
{
    const int row = blockIdx.x;
    const int tid = threadIdx.x;
    const int lane = tid & 31, wid = tid >> 5;
    const size_t off = (size_t)row * DD;
    const float swv = sw[row];

    float r0 = q[off + tid]       + ao[off + tid]       + swv * bv[tid];
    float r1 = q[off + tid + 256] + ao[off + tid + 256] + swv * bv[tid + 256];

    float s = warp_sum(r0 + r1);
    float ss = warp_sum(r0 * r0 + r1 * r1);
    __shared__ float rs[8], rss[8];
    if (lane == 0) { rs[wid] = s; rss[wid] = ss; }
    __syncthreads();
    __shared__ float mv[2];
    if (tid == 0) {
        float S = 0.f, SS = 0.f;
#pragma unroll
        for (int i = 0; i < 8; i++) { S += rs[i]; SS += rss[i]; }
        float mean = S * (1.f / 512.f);
        float var = SS * (1.f / 512.f) - mean * mean;
        mv[0] = mean; mv[1] = rsqrtf(var + EPS);
    }
    __syncthreads();
    const float mean = mv[0], inv = mv[1];
    float y0 = (r0 - mean) * inv * gamma[tid]       + beta[tid];
    float y1 = (r1 - mean) * inv * gamma[tid + 256] + beta[tid + 256];
    out[off + tid] = y0;
    out[off + tid + 256] = y1;
    __nv_bfloat16 h, l;
    split_bf16(y0, h, l); outh[off + tid] = h;       outl[off + tid] = l;
    split_bf16(y1, h, l); outh[off + tid + 256] = h; outl[off + tid + 256] = l;
}

// ---------------------------------------------------------------------------
// Fused residual + LayerNorm2 -> output
// ---------------------------------------------------------------------------
__global__ void __launch_bounds__(256) resid_ln_kernel(
    const float* __restrict__ a, const float* __restrict__ f,
    const float* __restrict__ gamma, const float* __restrict__ beta,
    float* __restrict__ out)
{
    const int row = blockIdx.x;
    const int tid = threadIdx.x;
    const int lane = tid & 31, wid = tid >> 5;
    const size_t off = (size_t)row * DD;

    float r0 = a[off + tid]       + f[off + tid];
    float r1 = a[off + tid + 256] + f[off + tid + 256];

    float s = warp_sum(r0 + r1);
    float ss = warp_sum(r0 * r0 + r1 * r1);
    __shared__ float rs[8], rss[8];
    if (lane == 0) { rs[wid] = s; rss[wid] = ss; }
    __syncthreads();
    __shared__ float mv[2];
    if (tid == 0) {
        float S = 0.f, SS = 0.f;
#pragma unroll
        for (int i = 0; i < 8; i++) { S += rs[i]; SS += rss[i]; }
        float mean = S * (1.f / 512.f);
        float var = SS * (1.f / 512.f) - mean * mean;
        mv[0] = mean; mv[1] = rsqrtf(var + EPS);
    }
    __syncthreads();
    const float mean = mv[0], inv = mv[1];
    out[off + tid]       = (r0 - mean) * inv * gamma[tid]       + beta[tid];
    out[off + tid + 256] = (r1 - mean) * inv * gamma[tid + 256] + beta[tid + 256];
}

// ---------------------------------------------------------------------------
// Launch
// ---------------------------------------------------------------------------
extern "C" void kernel_launch(void* const* d_in, const int* in_sizes, int n_in,
                              void* d_out, int out_size)
{
    const float* query  = (const float*)d_in[0];
    const float* key    = (const float*)d_in[1];
    const float* value  = (const float*)d_in[2];
    const float* w_q    = (const float*)d_in[3];
    const float* b_q    = (const float*)d_in[4];
    const float* w_k    = (const float*)d_in[5];
    const float* b_k    = (const float*)d_in[6];
    const float* w_v    = (const float*)d_in[7];
    const float* b_v    = (const float*)d_in[8];
    const float* ln1_g  = (const float*)d_in[9];
    const float* ln1_b  = (const float*)d_in[10];
    const float* ln2_g  = (const float*)d_in[11];
    const float* ln2_b  = (const float*)d_in[12];
    const float* ffn_w1 = (const float*)d_in[13];
    const float* ffn_b1 = (const float*)d_in[14];
    const float* ffn_w2 = (const float*)d_in[15];
    const float* ffn_b2 = (const float*)d_in[16];
    float* out = (float*)d_out;

    void* sp = nullptr;
    cudaGetSymbolAddress(&sp, g_scratch);
    float* s = (float*)sp;
    float* g_q    = s + F_Q;
    float* g_ao   = s + F_AO;
    float* g_out1 = s + F_O1;
    float* g_ffn  = s + F_FF;
    float* g_wp   = s + F_WP;
    float* g_sw   = s + F_SW;

    void* ap = nullptr;
    cudaGetSymbolAddress(&ap, g_act);
    __nv_bfloat16* a = (__nv_bfloat16*)ap;
    __nv_bfloat16* qh  = a + B_QH;  __nv_bfloat16* ql  = a + B_QL;
    __nv_bfloat16* kh  = a + B_KH;  __nv_bfloat16* kl  = a + B_KL;
    __nv_bfloat16* vh  = a + B_VH;  __nv_bfloat16* vl  = a + B_VL;
    __nv_bfloat16* o1h = a + B_O1H; __nv_bfloat16* o1l = a + B_O1L;
    __nv_bfloat16* hh  = a + B_HH;  __nv_bfloat16* hl  = a + B_HL;

    void* wp = nullptr;
    cudaGetSymbolAddress(&wp, g_wsplit);
    __nv_bfloat16* w = (__nv_bfloat16*)wp;
    const size_t WSZ = 512u * 512u;
    __nv_bfloat16* wqh = w + 0 * 2 * WSZ; __nv_bfloat16* wql = wqh + WSZ;
    __nv_bfloat16* wkh = w + 1 * 2 * WSZ; __nv_bfloat16* wkl = wkh + WSZ;
    __nv_bfloat16* wvh = w + 2 * 2 * WSZ; __nv_bfloat16* wvl = wvh + WSZ;
    __nv_bfloat16* f1h = w + 3 * 2 * WSZ; __nv_bfloat16* f1l = f1h + WSZ;
    __nv_bfloat16* f2h = w + 4 * 2 * WSZ; __nv_bfloat16* f2l = f2h + WSZ;

    cudaFuncSetAttribute((const void*)gemm_hl<true,  false, false, true >, cudaFuncAttributeMaxDynamicSharedMemorySize, GEMM_SMEM);
    cudaFuncSetAttribute((const void*)gemm_hl<true,  false, true,  true >, cudaFuncAttributeMaxDynamicSharedMemorySize, GEMM_SMEM);
    cudaFuncSetAttribute((const void*)gemm_hl<false, false, false, false>, cudaFuncAttributeMaxDynamicSharedMemorySize, GEMM_SMEM);
    cudaFuncSetAttribute((const void*)gemm_hl<true,  true,  false, true >, cudaFuncAttributeMaxDynamicSharedMemorySize, GEMM_SMEM);
    cudaFuncSetAttribute((const void*)gemm_hl<false, false, false, true >, cudaFuncAttributeMaxDynamicSharedMemorySize, GEMM_SMEM);

    const dim3 blk(256);

    prep_weight5<<<dim3(16, 16, 5), dim3(32, 8)>>>(w_q, w_k, w_v, ffn_w1, ffn_w2, w);
    f32_to_hl<<<NQ  * DD / 1024, blk>>>((const float4*)query, (uint2*)qh, (uint2*)ql);
    f32_to_hl<<<NKV * DD / 1024, blk>>>((const float4*)key,   (uint2*)kh, (uint2*)kl);

    const dim3 grid_q(DD / 128, NQ / 128);   // 4 x 64
    const dim3 grid_kv(DD / 128, NKV / 128); // 4 x 256

    // Q projection
    gemm_hl<true, false, false, true><<<grid_q, blk, GEMM_SMEM>>>(
        qh, ql, wqh, wql, b_q, g_q, nullptr, nullptr, nullptr, nullptr);

    // K projection with fused q.k dot -> w partials
    gemm_hl<true, false, true, true><<<grid_kv, blk, GEMM_SMEM>>>(
        kh, kl, wkh, wkl, b_k, nullptr, nullptr, nullptr, g_q, g_wp);

    // downsample raw value by w
    wds_kernel<<<NQ, blk>>>(g_wp, value, vh, vl, g_sw);

    // V projection on downsampled rows
    gemm_hl<false, false, false, false><<<grid_q, blk, GEMM_SMEM>>>(
        vh, vl, wvh, wvl, nullptr, g_ao, nullptr, nullptr, nullptr, nullptr);

    // LN1
    attn_ln_kernel<<<NQ, blk>>>(g_q, g_ao, g_sw, b_v, ln1_g, ln1_b, g_out1, o1h, o1l);

    // FFN
    gemm_hl<true, true, false, true><<<grid_q, blk, GEMM_SMEM>>>(
        o1h, o1l, f1h, f1l, ffn_b1, nullptr, hh, hl, nullptr, nullptr);
    gemm_hl<false, false, false, true><<<grid_q, blk, GEMM_SMEM>>>(
        hh, hl, f2h, f2l, ffn_b2, g_ffn, nullptr, nullptr, nullptr, nullptr);

    resid_ln_kernel<<<NQ, blk>>>(g_out1, g_ffn, ln2_g, ln2_b, out);
}

// round 7
// speedup vs baseline: 1.4611x; 1.0037x over previous
#include <cuda_runtime.h>
#include <cuda_bf16.h>
#include <cstdint>

// ---------------------------------------------------------------------------
// AttentionSampling: B=4, SQ=2048, SK=8192, D=H=512, F=4, fp32.
// GEMMs via mma.sync bf16 hi/lo 3-pass. Round 6: 2-stage pipeline (80KB smem)
// + <=128 regs so 2 CTAs/SM co-reside (was 1 -> tensor pipe 43% idle-bound).
// ---------------------------------------------------------------------------

#define DD 512
#define NQ  8192
#define NKV 32768
#define EPS 1e-5f

// fp32 scratch planes
#define F_Q   0
#define F_AO  (F_Q  + (size_t)NQ * DD)
#define F_O1  (F_AO + (size_t)NQ * DD)
#define F_FF  (F_O1 + (size_t)NQ * DD)
#define F_WP  (F_FF + (size_t)NQ * DD)          // w_part [NKV][16]
#define F_SW  (F_WP + (size_t)NKV * 16)         // sum-of-w [NQ]
#define F_TOT (F_SW + (size_t)NQ)
__device__ float g_scratch[F_TOT];

// bf16 hi/lo activation planes
#define B_QH  0
#define B_QL  (B_QH  + (size_t)NQ  * DD)
#define B_KH  (B_QL  + (size_t)NQ  * DD)
#define B_KL  (B_KH  + (size_t)NKV * DD)
#define B_VH  (B_KL  + (size_t)NKV * DD)        // downsampled value (NQ rows)
#define B_VL  (B_VH  + (size_t)NQ  * DD)
#define B_O1H (B_VL  + (size_t)NQ  * DD)
#define B_O1L (B_O1H + (size_t)NQ  * DD)
#define B_HH  (B_O1L + (size_t)NQ  * DD)
#define B_HL  (B_HH  + (size_t)NQ  * DD)
#define B_TOT (B_HL  + (size_t)NQ  * DD)
__device__ __nv_bfloat16 g_act[B_TOT];

// 5 weights x (hi,lo) x 512x512 bf16, stored [N][K] (transposed)
__device__ __nv_bfloat16 g_wsplit[5u * 2u * 512u * 512u];

// ---------------------------------------------------------------------------
// PTX helpers (base sm_100-legal)
// ---------------------------------------------------------------------------
__device__ __forceinline__ uint32_t smem_u32(const void* p) {
    uint32_t a;
    asm("{ .reg .u64 t; cvta.to.shared.u64 t, %1; cvt.u32.u64 %0, t; }"
        : "=r"(a) : "l"(p));
    return a;
}
__device__ __forceinline__ void ldsm_x4(uint32_t* r, uint32_t addr) {
    asm volatile("ldmatrix.sync.aligned.m8n8.x4.shared.b16 {%0,%1,%2,%3}, [%4];"
                 : "=r"(r[0]), "=r"(r[1]), "=r"(r[2]), "=r"(r[3]) : "r"(addr));
}
__device__ __forceinline__ void mma16816(float* c, const uint32_t* a, const uint32_t* b) {
    asm volatile(
        "mma.sync.aligned.m16n8k16.row.col.f32.bf16.bf16.f32 "
        "{%0,%1,%2,%3}, {%4,%5,%6,%7}, {%8,%9}, {%0,%1,%2,%3};"
        : "+f"(c[0]), "+f"(c[1]), "+f"(c[2]), "+f"(c[3])
        : "r"(a[0]), "r"(a[1]), "r"(a[2]), "r"(a[3]), "r"(b[0]), "r"(b[1]));
}
__device__ __forceinline__ void cp16(uint32_t saddr, const void* g) {
    asm volatile("cp.async.cg.shared.global [%0], [%1], 16;"
                 :: "r"(saddr), "l"(g) : "memory");
}
__device__ __forceinline__ void cp_commit() {
    asm volatile("cp.async.commit_group;" ::: "memory");
}
__device__ __forceinline__ void split_bf16(float x, __nv_bfloat16& h, __nv_bfloat16& l) {
    h = __float2bfloat16(x);
    l = __float2bfloat16(x - __bfloat162float(h));
}

// ---------------------------------------------------------------------------
// Batched weight prep: W[k][n] fp32 -> Th[n][k], Tl[n][k] bf16 (5 weights)
// ---------------------------------------------------------------------------
__global__ void prep_weight5(
    const float* w0, const float* w1, const float* w2, const float* w3, const float* w4,
    __nv_bfloat16* base)
{
    const float* Ws[5] = {w0, w1, w2, w3, w4};
    const size_t WSZ = 512u * 512u;
    const float* W = Ws[blockIdx.z];
    __nv_bfloat16* Th = base + (size_t)blockIdx.z * 2u * WSZ;
    __nv_bfloat16* Tl = Th + WSZ;

    __shared__ float t[32][33];
    const int bx = blockIdx.x * 32, by = blockIdx.y * 32;
    const int tx = threadIdx.x, ty = threadIdx.y; // 32 x 8
#pragma unroll
    for (int i = 0; i < 32; i += 8)
        t[ty + i][tx] = W[(size_t)(by + ty + i) * DD + bx + tx];
    __syncthreads();
#pragma unroll
    for (int i = 0; i < 32; i += 8) {
        float x = t[tx][ty + i];
        __nv_bfloat16 h, l;
        split_bf16(x, h, l);
        size_t o = (size_t)(bx + ty + i) * DD + by + tx;
        Th[o] = h;
        Tl[o] = l;
    }
}

// ---------------------------------------------------------------------------
// fp32 -> bf16 hi/lo split (vectorized)
// ---------------------------------------------------------------------------
__global__ void __launch_bounds__(256) f32_to_hl(
    const float4* __restrict__ src, uint2* __restrict__ dh, uint2* __restrict__ dl)
{
    const int i = blockIdx.x * 256 + threadIdx.x;
    float4 x = src[i];
    __nv_bfloat16 hx, hy, hz, hw, lx, ly, lz, lw;
    split_bf16(x.x, hx, lx); split_bf16(x.y, hy, ly);
    split_bf16(x.z, hz, lz); split_bf16(x.w, hw, lw);
    __nv_bfloat162 h01, h23, l01, l23;
    h01.x = hx; h01.y = hy; h23.x = hz; h23.y = hw;
    l01.x = lx; l01.y = ly; l23.x = lz; l23.y = lw;
    uint2 hv, lv;
    hv.x = *(uint32_t*)&h01; hv.y = *(uint32_t*)&h23;
    lv.x = *(uint32_t*)&l01; lv.y = *(uint32_t*)&l23;
    dh[i] = hv;
    dl[i] = lv;
}

// ---------------------------------------------------------------------------
// HMMA GEMM: act(A[M,512] @ W[512,512] + bias)
// BM=128, BN=128, BK=32, 256 thr (8 warps 2m x 4n; warp tile 64x32).
// 2-stage cp.async pipeline (80KB) + launch_bounds(256,2) -> 2 CTAs/SM.
// DOTQ: k rows dotted with q rows instead of stored (w partials out).
// ---------------------------------------------------------------------------
#define BKC 32
#define NCH (DD / BKC)          // 16
#define RSTRB 80
#define PLANE (128 * RSTRB)
#define SG_AH 0
#define SG_AL (1 * PLANE)
#define SG_BH (2 * PLANE)
#define SG_BL (3 * PLANE)
#define SG_SZ (4 * PLANE)       // 40960
#define STAGES 2
#define GEMM_SMEM (STAGES * SG_SZ) // 81920

template <bool RELU, bool OUT_HL, bool DOTQ, bool HASBIAS>
__global__ void __launch_bounds__(256, 2) gemm_hl(
    const __nv_bfloat16* __restrict__ Ah, const __nv_bfloat16* __restrict__ Al,
    const __nv_bfloat16* __restrict__ Bh, const __nv_bfloat16* __restrict__ Bl,
    const float* __restrict__ bias, float* __restrict__ C,
    __nv_bfloat16* __restrict__ Ch, __nv_bfloat16* __restrict__ Cl,
    const float* __restrict__ qdot, float* __restrict__ wpart)
{
    extern __shared__ char sm[];
    const uint32_t sb = smem_u32(sm);

    const int tid = threadIdx.x;
    const int lane = tid & 31, wid = tid >> 5;
    const int wm = (wid & 1) * 64;
    const int wn = (wid >> 1) * 32;
    const int bm = blockIdx.y * 128;
    const int bn = blockIdx.x * 128;

    float acc[4][4][4];
#pragma unroll
    for (int i = 0; i < 4; i++)
#pragma unroll
        for (int j = 0; j < 4; j++)
#pragma unroll
            for (int t = 0; t < 4; t++) acc[i][j][t] = 0.f;

    const int row0 = tid >> 2, seg0 = tid & 3;
    const int row1 = (tid + 256) >> 2, seg1 = tid & 3;

    auto load_stage = [&](int c, int buf) {
        const uint32_t st = sb + buf * SG_SZ;
        const int kc = c * BKC;
        {
            uint32_t so = (uint32_t)row0 * RSTRB + seg0 * 16;
            size_t ga = (size_t)(bm + row0) * DD + kc + seg0 * 8;
            size_t gb = (size_t)(bn + row0) * DD + kc + seg0 * 8;
            cp16(st + SG_AH + so, Ah + ga);
            cp16(st + SG_AL + so, Al + ga);
            cp16(st + SG_BH + so, Bh + gb);
            cp16(st + SG_BL + so, Bl + gb);
        }
        {
            uint32_t so = (uint32_t)row1 * RSTRB + seg1 * 16;
            size_t ga = (size_t)(bm + row1) * DD + kc + seg1 * 8;
            size_t gb = (size_t)(bn + row1) * DD + kc + seg1 * 8;
            cp16(st + SG_AH + so, Ah + ga);
            cp16(st + SG_AL + so, Al + ga);
            cp16(st + SG_BH + so, Bh + gb);
            cp16(st + SG_BL + so, Bl + gb);
        }
        cp_commit();
    };

    const int a_r = wm + (lane & 15);
    const int a_cb = (lane >> 4) * 16;
    const int b_r = wn + ((lane >> 4) << 3) + (lane & 7);
    const int b_cb = ((lane >> 3) & 1) * 16;

    // single frag buffer (register budget: 2 CTAs/SM needs <=128 regs)
    auto compute = [&](int buf) {
        const uint32_t st = sb + buf * SG_SZ;
#pragma unroll
        for (int ks = 0; ks < 2; ks++) {
            uint32_t ah[4][4], al[4][4], bh[2][4], bl[2][4];
            const uint32_t kb = (uint32_t)(ks * 32);
#pragma unroll
            for (int i = 0; i < 4; i++) {
                uint32_t off = (uint32_t)(a_r + i * 16) * RSTRB + kb + a_cb;
                ldsm_x4(ah[i], st + SG_AH + off);
                ldsm_x4(al[i], st + SG_AL + off);
            }
#pragma unroll
            for (int jp = 0; jp < 2; jp++) {
                uint32_t off = (uint32_t)(b_r + jp * 16) * RSTRB + kb + b_cb;
                ldsm_x4(bh[jp], st + SG_BH + off);
                ldsm_x4(bl[jp], st + SG_BL + off);
            }
#pragma unroll
            for (int i = 0; i < 4; i++)
#pragma unroll
                for (int j = 0; j < 4; j++)
                    mma16816(acc[i][j], ah[i], &bh[j >> 1][(j & 1) * 2]);
#pragma unroll
            for (int i = 0; i < 4; i++)
#pragma unroll
                for (int j = 0; j < 4; j++)
                    mma16816(acc[i][j], ah[i], &bl[j >> 1][(j & 1) * 2]);
#pragma unroll
            for (int i = 0; i < 4; i++)
#pragma unroll
                for (int j = 0; j < 4; j++)
                    mma16816(acc[i][j], al[i], &bh[j >> 1][(j & 1) * 2]);
        }
    };

    // 2-stage pipeline
    load_stage(0, 0);
    load_stage(1, 1);

#pragma unroll 1
    for (int c = 0; c < NCH; c++) {
        if (c < NCH - 2)
            asm volatile("cp.async.wait_group 1;" ::: "memory");
        else
            asm volatile("cp.async.wait_group 0;" ::: "memory");
        __syncthreads();
        compute(c & 1);
        if (c + 2 < NCH) {
            __syncthreads();
            load_stage(c + 2, c & 1);
        }
    }

    // ---------------- epilogue ----------------
    const int crow = lane >> 2, ccol = (lane & 3) * 2;

    if (DOTQ) {
        float dotr[4][2];
#pragma unroll
        for (int i = 0; i < 4; i++) { dotr[i][0] = 0.f; dotr[i][1] = 0.f; }
#pragma unroll
        for (int i = 0; i < 4; i++) {
            const int r0 = bm + wm + i * 16 + crow;
            const float* q0p = qdot + (size_t)(r0 >> 2) * DD;
            const float* q1p = qdot + (size_t)((r0 + 8) >> 2) * DD;
#pragma unroll
            for (int j = 0; j < 4; j++) {
                const int col = bn + wn + j * 8 + ccol;
                float bx = 0.f, by = 0.f;
                if (HASBIAS) {
                    float2 bv = *(const float2*)(bias + col);
                    bx = bv.x; by = bv.y;
                }
                float k00 = fmaxf(acc[i][j][0] + bx, 0.f);
                float k01 = fmaxf(acc[i][j][1] + by, 0.f);
                float k10 = fmaxf(acc[i][j][2] + bx, 0.f);
                float k11 = fmaxf(acc[i][j][3] + by, 0.f);
                float2 q0 = *(const float2*)(q0p + col);
                float2 q1 = *(const float2*)(q1p + col);
                dotr[i][0] += k00 * q0.x + k01 * q0.y;
                dotr[i][1] += k10 * q1.x + k11 * q1.y;
            }
        }
#pragma unroll
        for (int i = 0; i < 4; i++)
#pragma unroll
            for (int p = 0; p < 2; p++) {
                float v = dotr[i][p];
                v += __shfl_xor_sync(0xffffffffu, v, 1);
                v += __shfl_xor_sync(0xffffffffu, v, 2);
                if ((lane & 3) == 0) {
                    const int row = bm + wm + i * 16 + crow + p * 8;
                    wpart[(size_t)row * 16 + blockIdx.x * 4 + (wid >> 1)] = v;
                }
            }
        return;
    }

#pragma unroll
    for (int i = 0; i < 4; i++) {
        const int r0 = bm + wm + i * 16 + crow;
#pragma unroll
        for (int j = 0; j < 4; j++) {
            const int col = bn + wn + j * 8 + ccol;
            float bx = 0.f, by = 0.f;
            if (HASBIAS) {
                float2 bv = *(const float2*)(bias + col);
                bx = bv.x; by = bv.y;
            }
            float2 o0, o1;
            o0.x = acc[i][j][0] + bx; o0.y = acc[i][j][1] + by;
            o1.x = acc[i][j][2] + bx; o1.y = acc[i][j][3] + by;
            if (RELU) {
                o0.x = fmaxf(o0.x, 0.f); o0.y = fmaxf(o0.y, 0.f);
                o1.x = fmaxf(o1.x, 0.f); o1.y = fmaxf(o1.y, 0.f);
            }
            if (OUT_HL) {
                __nv_bfloat162 h2, l2;
                split_bf16(o0.x, h2.x, l2.x); split_bf16(o0.y, h2.y, l2.y);
                *(__nv_bfloat162*)(Ch + (size_t)r0 * DD + col) = h2;
                *(__nv_bfloat162*)(Cl + (size_t)r0 * DD + col) = l2;
                split_bf16(o1.x, h2.x, l2.x); split_bf16(o1.y, h2.y, l2.y);
                *(__nv_bfloat162*)(Ch + (size_t)(r0 + 8) * DD + col) = h2;
                *(__nv_bfloat162*)(Cl + (size_t)(r0 + 8) * DD + col) = l2;
            } else {
                *(float2*)(C + (size_t)r0 * DD + col) = o0;
                *(float2*)(C + (size_t)(r0 + 8) * DD + col) = o1;
            }
        }
    }
}

// ---------------------------------------------------------------------------
// Downsample: vds[s,:] = sum_f w[4s+f] * value[4s+f,:]; sw[s] = sum_f w.
// ---------------------------------------------------------------------------
__global__ void __launch_bounds__(256) wds_kernel(
    const float* __restrict__ wpart, const float* __restrict__ value,
    __nv_bfloat16* __restrict__ vh, __nv_bfloat16* __restrict__ vl,
    float* __restrict__ sw)
{
    const int s = blockIdx.x;
    const int tid = threadIdx.x;
    __shared__ float wp[64];
    __shared__ float wf[4];
    if (tid < 64) wp[tid] = wpart[(size_t)s * 64 + tid];
    __syncthreads();
    if (tid < 4) {
        float a = 0.f;
#pragma unroll
        for (int p = 0; p < 16; p++) a += wp[tid * 16 + p];
        wf[tid] = a;
    }
    __syncthreads();
    const float w0 = wf[0], w1 = wf[1], w2 = wf[2], w3 = wf[3];
    if (tid == 0) sw[s] = w0 + w1 + w2 + w3;

    const float* vr = value + (size_t)s * 4 * DD;
    const size_t o = (size_t)s * DD;
#pragma unroll
    for (int u = 0; u < 2; u++) {
        const int d = tid + u * 256;
        float x = w0 * vr[d] + w1 * vr[DD + d] + w2 * vr[2 * DD + d] + w3 * vr[3 * DD + d];
        __nv_bfloat16 h, l;
        split_bf16(x, h, l);
        vh[o + d] = h;
        vl[o + d] = l;
    }
}

// ---------------------------------------------------------------------------
// warp reduction
// ---------------------------------------------------------------------------
__device__ __forceinline__ float warp_sum(float x) {
#pragma unroll
    for (int o = 16; o > 0; o >>= 1) x += __shfl_xor_sync(0xffffffffu, x, o);
    return x;
}

// ---------------------------------------------------------------------------
// LN1: r = q + ao + sw*b_v; out1 = LN(r) (fp32 + bf16 hi/lo)
// ---------------------------------------------------------------------------
__global__ void __launch_bounds__(256) attn_ln_kernel(
    const float* __restrict__ q, const float* __restrict__ ao,
    const float* __restrict__ sw, const float* __restrict__ bv,
    const float* __restrict__ gamma, const float* __restrict__ beta,
    float* __restrict__ out,
    __nv_bfloat16* __restrict__ outh, __nv_bfloat16* __restrict__ outl)
{
    const int row = blockIdx.x;
    const int tid = threadIdx.x;
    const int lane = tid & 31, wid = tid >> 5;
    const size_t off = (size_t)row * DD;
    const float swv = sw[row];

    float r0 = q[off + tid]       + ao[off + tid]       + swv * bv[tid];
    float r1 = q[off + tid + 256] + ao[off + tid + 256] + swv * bv[tid + 256];

    float s = warp_sum(r0 + r1);
    float ss = warp_sum(r0 * r0 + r1 * r1);
    __shared__ float rs[8], rss[8];
    if (lane == 0) { rs[wid] = s; rss[wid] = ss; }
    __syncthreads();
    __shared__ float mv[2];
    if (tid == 0) {
        float S = 0.f, SS = 0.f;
#pragma unroll
        for (int i = 0; i < 8; i++) { S += rs[i]; SS += rss[i]; }
        float mean = S * (1.f / 512.f);
        float var = SS * (1.f / 512.f) - mean * mean;
        mv[0] = mean; mv[1] = rsqrtf(var + EPS);
    }
    __syncthreads();
    const float mean = mv[0], inv = mv[1];
    float y0 = (r0 - mean) * inv * gamma[tid]       + beta[tid];
    float y1 = (r1 - mean) * inv * gamma[tid + 256] + beta[tid + 256];
    out[off + tid] = y0;
    out[off + tid + 256] = y1;
    __nv_bfloat16 h, l;
    split_bf16(y0, h, l); outh[off + tid] = h;       outl[off + tid] = l;
    split_bf16(y1, h, l); outh[off + tid + 256] = h; outl[off + tid + 256] = l;
}

// ---------------------------------------------------------------------------
// Fused residual + LayerNorm2 -> output
// ---------------------------------------------------------------------------
__global__ void __launch_bounds__(256) resid_ln_kernel(
    const float* __restrict__ a, const float* __restrict__ f,
    const float* __restrict__ gamma, const float* __restrict__ beta,
    float* __restrict__ out)
{
    const int row = blockIdx.x;
    const int tid = threadIdx.x;
    const int lane = tid & 31, wid = tid >> 5;
    const size_t off = (size_t)row * DD;

    float r0 = a[off + tid]       + f[off + tid];
    float r1 = a[off + tid + 256] + f[off + tid + 256];

    float s = warp_sum(r0 + r1);
    float ss = warp_sum(r0 * r0 + r1 * r1);
    __shared__ float rs[8], rss[8];
    if (lane == 0) { rs[wid] = s; rss[wid] = ss; }
    __syncthreads();
    __shared__ float mv[2];
    if (tid == 0) {
        float S = 0.f, SS = 0.f;
#pragma unroll
        for (int i = 0; i < 8; i++) { S += rs[i]; SS += rss[i]; }
        float mean = S * (1.f / 512.f);
        float var = SS * (1.f / 512.f) - mean * mean;
        mv[0] = mean; mv[1] = rsqrtf(var + EPS);
    }
    __syncthreads();
    const float mean = mv[0], inv = mv[1];
    out[off + tid]       = (r0 - mean) * inv * gamma[tid]       + beta[tid];
    out[off + tid + 256] = (r1 - mean) * inv * gamma[tid + 256] + beta[tid + 256];
}

// ---------------------------------------------------------------------------
// Launch
// ---------------------------------------------------------------------------
extern "C" void kernel_launch(void* const* d_in, const int* in_sizes, int n_in,
                              void* d_out, int out_size)
{
    const float* query  = (const float*)d_in[0];
    const float* key    = (const float*)d_in[1];
    const float* value  = (const float*)d_in[2];
    const float* w_q    = (const float*)d_in[3];
    const float* b_q    = (const float*)d_in[4];
    const float* w_k    = (const float*)d_in[5];
    const float* b_k    = (const float*)d_in[6];
    const float* w_v    = (const float*)d_in[7];
    const float* b_v    = (const float*)d_in[8];
    const float* ln1_g  = (const float*)d_in[9];
    const float* ln1_b  = (const float*)d_in[10];
    const float* ln2_g  = (const float*)d_in[11];
    const float* ln2_b  = (const float*)d_in[12];
    const float* ffn_w1 = (const float*)d_in[13];
    const float* ffn_b1 = (const float*)d_in[14];
    const float* ffn_w2 = (const float*)d_in[15];
    const float* ffn_b2 = (const float*)d_in[16];
    float* out = (float*)d_out;

    void* sp = nullptr;
    cudaGetSymbolAddress(&sp, g_scratch);
    float* s = (float*)sp;
    float* g_q    = s + F_Q;
    float* g_ao   = s + F_AO;
    float* g_out1 = s + F_O1;
    float* g_ffn  = s + F_FF;
    float* g_wp   = s + F_WP;
    float* g_sw   = s + F_SW;

    void* ap = nullptr;
    cudaGetSymbolAddress(&ap, g_act);
    __nv_bfloat16* a = (__nv_bfloat16*)ap;
    __nv_bfloat16* qh  = a + B_QH;  __nv_bfloat16* ql  = a + B_QL;
    __nv_bfloat16* kh  = a + B_KH;  __nv_bfloat16* kl  = a + B_KL;
    __nv_bfloat16* vh  = a + B_VH;  __nv_bfloat16* vl  = a + B_VL;
    __nv_bfloat16* o1h = a + B_O1H; __nv_bfloat16* o1l = a + B_O1L;
    __nv_bfloat16* hh  = a + B_HH;  __nv_bfloat16* hl  = a + B_HL;

    void* wp = nullptr;
    cudaGetSymbolAddress(&wp, g_wsplit);
    __nv_bfloat16* w = (__nv_bfloat16*)wp;
    const size_t WSZ = 512u * 512u;
    __nv_bfloat16* wqh = w + 0 * 2 * WSZ; __nv_bfloat16* wql = wqh + WSZ;
    __nv_bfloat16* wkh = w + 1 * 2 * WSZ; __nv_bfloat16* wkl = wkh + WSZ;
    __nv_bfloat16* wvh = w + 2 * 2 * WSZ; __nv_bfloat16* wvl = wvh + WSZ;
    __nv_bfloat16* f1h = w + 3 * 2 * WSZ; __nv_bfloat16* f1l = f1h + WSZ;
    __nv_bfloat16* f2h = w + 4 * 2 * WSZ; __nv_bfloat16* f2l = f2h + WSZ;

    cudaFuncSetAttribute((const void*)gemm_hl<true,  false, false, true >, cudaFuncAttributeMaxDynamicSharedMemorySize, GEMM_SMEM);
    cudaFuncSetAttribute((const void*)gemm_hl<true,  false, true,  true >, cudaFuncAttributeMaxDynamicSharedMemorySize, GEMM_SMEM);
    cudaFuncSetAttribute((const void*)gemm_hl<false, false, false, false>, cudaFuncAttributeMaxDynamicSharedMemorySize, GEMM_SMEM);
    cudaFuncSetAttribute((const void*)gemm_hl<true,  true,  false, true >, cudaFuncAttributeMaxDynamicSharedMemorySize, GEMM_SMEM);
    cudaFuncSetAttribute((const void*)gemm_hl<false, false, false, true >, cudaFuncAttributeMaxDynamicSharedMemorySize, GEMM_SMEM);

    const dim3 blk(256);

    prep_weight5<<<dim3(16, 16, 5), dim3(32, 8)>>>(w_q, w_k, w_v, ffn_w1, ffn_w2, w);
    f32_to_hl<<<NQ  * DD / 1024, blk>>>((const float4*)query, (uint2*)qh, (uint2*)ql);
    f32_to_hl<<<NKV * DD / 1024, blk>>>((const float4*)key,   (uint2*)kh, (uint2*)kl);

    const dim3 grid_q(DD / 128, NQ / 128);   // 4 x 64
    const dim3 grid_kv(DD / 128, NKV / 128); // 4 x 256

    // Q projection
    gemm_hl<true, false, false, true><<<grid_q, blk, GEMM_SMEM>>>(
        qh, ql, wqh, wql, b_q, g_q, nullptr, nullptr, nullptr, nullptr);

    // K projection with fused q.k dot -> w partials
    gemm_hl<true, false, true, true><<<grid_kv, blk, GEMM_SMEM>>>(
        kh, kl, wkh, wkl, b_k, nullptr, nullptr, nullptr, g_q, g_wp);

    // downsample raw value by w
    wds_kernel<<<NQ, blk>>>(g_wp, value, vh, vl, g_sw);

    // V projection on downsampled rows
    gemm_hl<false, false, false, false><<<grid_q, blk, GEMM_SMEM>>>(
        vh, vl, wvh, wvl, nullptr, g_ao, nullptr, nullptr, nullptr, nullptr);

    // LN1
    attn_ln_kernel<<<NQ, blk>>>(g_q, g_ao, g_sw, b_v, ln1_g, ln1_b, g_out1, o1h, o1l);

    // FFN
    gemm_hl<true, true, false, true><<<grid_q, blk, GEMM_SMEM>>>(
        o1h, o1l, f1h, f1l, ffn_b1, nullptr, hh, hl, nullptr, nullptr);
    gemm_hl<false, false, false, true><<<grid_q, blk, GEMM_SMEM>>>(
        hh, hl, f2h, f2l, ffn_b2, g_ffn, nullptr, nullptr, nullptr, nullptr);

    resid_ln_kernel<<<NQ, blk>>>(g_out1, g_ffn, ln2_g, ln2_b, out);
}

// round 8
// speedup vs baseline: 1.6573x; 1.1343x over previous
#include <cuda_runtime.h>
#include <cuda_bf16.h>
#include <cstdint>

// ---------------------------------------------------------------------------
// AttentionSampling: B=4, SQ=2048, SK=8192, D=H=512, F=4, fp32.
// GEMMs via mma.sync bf16 hi/lo 3-pass. Round 8: XOR-swizzled 64B rows
// (no pad), 3-stage cp.async pipeline in 96KB, ONE barrier per chunk,
// 2 CTAs/SM.
// ---------------------------------------------------------------------------

#define DD 512
#define NQ  8192
#define NKV 32768
#define EPS 1e-5f

// fp32 scratch planes
#define F_Q   0
#define F_AO  (F_Q  + (size_t)NQ * DD)
#define F_O1  (F_AO + (size_t)NQ * DD)
#define F_FF  (F_O1 + (size_t)NQ * DD)
#define F_WP  (F_FF + (size_t)NQ * DD)          // w_part [NKV][16]
#define F_SW  (F_WP + (size_t)NKV * 16)         // sum-of-w [NQ]
#define F_TOT (F_SW + (size_t)NQ)
__device__ float g_scratch[F_TOT];

// bf16 hi/lo activation planes
#define B_QH  0
#define B_QL  (B_QH  + (size_t)NQ  * DD)
#define B_KH  (B_QL  + (size_t)NQ  * DD)
#define B_KL  (B_KH  + (size_t)NKV * DD)
#define B_VH  (B_KL  + (size_t)NKV * DD)        // downsampled value (NQ rows)
#define B_VL  (B_VH  + (size_t)NQ  * DD)
#define B_O1H (B_VL  + (size_t)NQ  * DD)
#define B_O1L (B_O1H + (size_t)NQ  * DD)
#define B_HH  (B_O1L + (size_t)NQ  * DD)
#define B_HL  (B_HH  + (size_t)NQ  * DD)
#define B_TOT (B_HL  + (size_t)NQ  * DD)
__device__ __nv_bfloat16 g_act[B_TOT];

// 5 weights x (hi,lo) x 512x512 bf16, stored [N][K] (transposed)
__device__ __nv_bfloat16 g_wsplit[5u * 2u * 512u * 512u];

// ---------------------------------------------------------------------------
// PTX helpers (base sm_100-legal)
// ---------------------------------------------------------------------------
__device__ __forceinline__ uint32_t smem_u32(const void* p) {
    uint32_t a;
    asm("{ .reg .u64 t; cvta.to.shared.u64 t, %1; cvt.u32.u64 %0, t; }"
        : "=r"(a) : "l"(p));
    return a;
}
__device__ __forceinline__ void ldsm_x4(uint32_t* r, uint32_t addr) {
    asm volatile("ldmatrix.sync.aligned.m8n8.x4.shared.b16 {%0,%1,%2,%3}, [%4];"
                 : "=r"(r[0]), "=r"(r[1]), "=r"(r[2]), "=r"(r[3]) : "r"(addr));
}
__device__ __forceinline__ void mma16816(float* c, const uint32_t* a, const uint32_t* b) {
    asm volatile(
        "mma.sync.aligned.m16n8k16.row.col.f32.bf16.bf16.f32 "
        "{%0,%1,%2,%3}, {%4,%5,%6,%7}, {%8,%9}, {%0,%1,%2,%3};"
        : "+f"(c[0]), "+f"(c[1]), "+f"(c[2]), "+f"(c[3])
        : "r"(a[0]), "r"(a[1]), "r"(a[2]), "r"(a[3]), "r"(b[0]), "r"(b[1]));
}
__device__ __forceinline__ void cp16(uint32_t saddr, const void* g) {
    asm volatile("cp.async.cg.shared.global [%0], [%1], 16;"
                 :: "r"(saddr), "l"(g) : "memory");
}
__device__ __forceinline__ void cp_commit() {
    asm volatile("cp.async.commit_group;" ::: "memory");
}
__device__ __forceinline__ void split_bf16(float x, __nv_bfloat16& h, __nv_bfloat16& l) {
    h = __float2bfloat16(x);
    l = __float2bfloat16(x - __bfloat162float(h));
}

// swizzled byte offset of 16B chunk (row, chunk) in a 128x64B plane
__device__ __forceinline__ uint32_t swz_off(uint32_t row, uint32_t chunk) {
    return row * 64u + ((chunk ^ ((row >> 1) & 3u)) << 4);
}

// ---------------------------------------------------------------------------
// Batched weight prep: W[k][n] fp32 -> Th[n][k], Tl[n][k] bf16 (5 weights)
// ---------------------------------------------------------------------------
__global__ void prep_weight5(
    const float* w0, const float* w1, const float* w2, const float* w3, const float* w4,
    __nv_bfloat16* base)
{
    const float* Ws[5] = {w0, w1, w2, w3, w4};
    const size_t WSZ = 512u * 512u;
    const float* W = Ws[blockIdx.z];
    __nv_bfloat16* Th = base + (size_t)blockIdx.z * 2u * WSZ;
    __nv_bfloat16* Tl = Th + WSZ;

    __shared__ float t[32][33];
    const int bx = blockIdx.x * 32, by = blockIdx.y * 32;
    const int tx = threadIdx.x, ty = threadIdx.y; // 32 x 8
#pragma unroll
    for (int i = 0; i < 32; i += 8)
        t[ty + i][tx] = W[(size_t)(by + ty + i) * DD + bx + tx];
    __syncthreads();
#pragma unroll
    for (int i = 0; i < 32; i += 8) {
        float x = t[tx][ty + i];
        __nv_bfloat16 h, l;
        split_bf16(x, h, l);
        size_t o = (size_t)(bx + ty + i) * DD + by + tx;
        Th[o] = h;
        Tl[o] = l;
    }
}

// ---------------------------------------------------------------------------
// fp32 -> bf16 hi/lo split (vectorized)
// ---------------------------------------------------------------------------
__global__ void __launch_bounds__(256) f32_to_hl(
    const float4* __restrict__ src, uint2* __restrict__ dh, uint2* __restrict__ dl)
{
    const int i = blockIdx.x * 256 + threadIdx.x;
    float4 x = src[i];
    __nv_bfloat16 hx, hy, hz, hw, lx, ly, lz, lw;
    split_bf16(x.x, hx, lx); split_bf16(x.y, hy, ly);
    split_bf16(x.z, hz, lz); split_bf16(x.w, hw, lw);
    __nv_bfloat162 h01, h23, l01, l23;
    h01.x = hx; h01.y = hy; h23.x = hz; h23.y = hw;
    l01.x = lx; l01.y = ly; l23.x = lz; l23.y = lw;
    uint2 hv, lv;
    hv.x = *(uint32_t*)&h01; hv.y = *(uint32_t*)&h23;
    lv.x = *(uint32_t*)&l01; lv.y = *(uint32_t*)&l23;
    dh[i] = hv;
    dl[i] = lv;
}

// ---------------------------------------------------------------------------
// HMMA GEMM: act(A[M,512] @ W[512,512] + bias)
// BM=128, BN=128, BK=32, 256 thr (8 warps 2m x 4n; warp tile 64x32).
// 3-stage cp.async pipeline, XOR-swizzled 64B rows, 1 barrier/chunk,
// launch_bounds(256,2) -> 2 CTAs/SM.
// DOTQ: k rows dotted with q rows instead of stored (w partials out).
// ---------------------------------------------------------------------------
#define BKC 32
#define NCH (DD / BKC)          // 16
#define PLANE 8192              // 128 rows x 64B, swizzled
#define SG_AH 0
#define SG_AL (1 * PLANE)
#define SG_BH (2 * PLANE)
#define SG_BL (3 * PLANE)
#define SG_SZ (4 * PLANE)       // 32768
#define STAGES 3
#define GEMM_SMEM (STAGES * SG_SZ) // 98304

template <bool RELU, bool OUT_HL, bool DOTQ, bool HASBIAS>
__global__ void __launch_bounds__(256, 2) gemm_hl(
    const __nv_bfloat16* __restrict__ Ah, const __nv_bfloat16* __restrict__ Al,
    const __nv_bfloat16* __restrict__ Bh, const __nv_bfloat16* __restrict__ Bl,
    const float* __restrict__ bias, float* __restrict__ C,
    __nv_bfloat16* __restrict__ Ch, __nv_bfloat16* __restrict__ Cl,
    const float* __restrict__ qdot, float* __restrict__ wpart)
{
    extern __shared__ char sm[];
    const uint32_t sb = smem_u32(sm);

    const int tid = threadIdx.x;
    const int lane = tid & 31, wid = tid >> 5;
    const int wm = (wid & 1) * 64;
    const int wn = (wid >> 1) * 32;
    const int bm = blockIdx.y * 128;
    const int bn = blockIdx.x * 128;

    float acc[4][4][4];
#pragma unroll
    for (int i = 0; i < 4; i++)
#pragma unroll
        for (int j = 0; j < 4; j++)
#pragma unroll
            for (int t = 0; t < 4; t++) acc[i][j][t] = 0.f;

    const uint32_t row0 = (uint32_t)(tid >> 2), seg0 = (uint32_t)(tid & 3);
    const uint32_t row1 = row0 + 64;

    auto load_stage = [&](int c, int buf) {
        const uint32_t st = sb + buf * SG_SZ;
        const int kc = c * BKC;
        {
            uint32_t so = swz_off(row0, seg0);
            size_t ga = (size_t)(bm + row0) * DD + kc + seg0 * 8;
            size_t gb = (size_t)(bn + row0) * DD + kc + seg0 * 8;
            cp16(st + SG_AH + so, Ah + ga);
            cp16(st + SG_AL + so, Al + ga);
            cp16(st + SG_BH + so, Bh + gb);
            cp16(st + SG_BL + so, Bl + gb);
        }
        {
            uint32_t so = swz_off(row1, seg0);
            size_t ga = (size_t)(bm + row1) * DD + kc + seg0 * 8;
            size_t gb = (size_t)(bn + row1) * DD + kc + seg0 * 8;
            cp16(st + SG_AH + so, Ah + ga);
            cp16(st + SG_AL + so, Al + ga);
            cp16(st + SG_BH + so, Bh + gb);
            cp16(st + SG_BL + so, Bl + gb);
        }
        cp_commit();
    };

    const uint32_t a_r = (uint32_t)(wm + (lane & 15));
    const uint32_t a_ch = (uint32_t)(lane >> 4);        // chunk half (0/1)
    const uint32_t b_r = (uint32_t)(wn + ((lane >> 4) << 3) + (lane & 7));
    const uint32_t b_ch = (uint32_t)((lane >> 3) & 1);

    auto compute = [&](int buf) {
        const uint32_t st = sb + buf * SG_SZ;
#pragma unroll
        for (int ks = 0; ks < 2; ks++) {
            uint32_t ah[4][4], al[4][4], bh[2][4], bl[2][4];
            const uint32_t kch = (uint32_t)(ks * 2);
#pragma unroll
            for (int i = 0; i < 4; i++) {
                uint32_t off = swz_off(a_r + i * 16, kch + a_ch);
                ldsm_x4(ah[i], st + SG_AH + off);
                ldsm_x4(al[i], st + SG_AL + off);
            }
#pragma unroll
            for (int jp = 0; jp < 2; jp++) {
                uint32_t off = swz_off(b_r + jp * 16, kch + b_ch);
                ldsm_x4(bh[jp], st + SG_BH + off);
                ldsm_x4(bl[jp], st + SG_BL + off);
            }
#pragma unroll
            for (int i = 0; i < 4; i++)
#pragma unroll
                for (int j = 0; j < 4; j++)
                    mma16816(acc[i][j], ah[i], &bh[j >> 1][(j & 1) * 2]);
#pragma unroll
            for (int i = 0; i < 4; i++)
#pragma unroll
                for (int j = 0; j < 4; j++)
                    mma16816(acc[i][j], ah[i], &bl[j >> 1][(j & 1) * 2]);
#pragma unroll
            for (int i = 0; i < 4; i++)
#pragma unroll
                for (int j = 0; j < 4; j++)
                    mma16816(acc[i][j], al[i], &bh[j >> 1][(j & 1) * 2]);
        }
    };

    // 3-stage pipeline, one barrier per chunk.
    // Prologue: chunks 0,1 in flight. At iter c: wait chunk c, sync,
    // issue chunk c+2 into buffer (c+2)%3 (retired at iter c-1), compute c.
    load_stage(0, 0);
    load_stage(1, 1);

#pragma unroll 1
    for (int c = 0; c < NCH; c++) {
        if (c < NCH - 1)
            asm volatile("cp.async.wait_group 1;" ::: "memory");
        else
            asm volatile("cp.async.wait_group 0;" ::: "memory");
        __syncthreads();
        if (c + 2 < NCH) load_stage(c + 2, (c + 2) % 3);
        compute(c % 3);
    }

    // ---------------- epilogue ----------------
    const int crow = lane >> 2, ccol = (lane & 3) * 2;

    if (DOTQ) {
        float dotr[4][2];
#pragma unroll
        for (int i = 0; i < 4; i++) { dotr[i][0] = 0.f; dotr[i][1] = 0.f; }
#pragma unroll
        for (int i = 0; i < 4; i++) {
            const int r0 = bm + wm + i * 16 + crow;
            const float* q0p = qdot + (size_t)(r0 >> 2) * DD;
            const float* q1p = qdot + (size_t)((r0 + 8) >> 2) * DD;
#pragma unroll
            for (int j = 0; j < 4; j++) {
                const int col = bn + wn + j * 8 + ccol;
                float bx = 0.f, by = 0.f;
                if (HASBIAS) {
                    float2 bv = *(const float2*)(bias + col);
                    bx = bv.x; by = bv.y;
                }
                float k00 = fmaxf(acc[i][j][0] + bx, 0.f);
                float k01 = fmaxf(acc[i][j][1] + by, 0.f);
                float k10 = fmaxf(acc[i][j][2] + bx, 0.f);
                float k11 = fmaxf(acc[i][j][3] + by, 0.f);
                float2 q0 = *(const float2*)(q0p + col);
                float2 q1 = *(const float2*)(q1p + col);
                dotr[i][0] += k00 * q0.x + k01 * q0.y;
                dotr[i][1] += k10 * q1.x + k11 * q1.y;
            }
        }
#pragma unroll
        for (int i = 0; i < 4; i++)
#pragma unroll
            for (int p = 0; p < 2; p++) {
                float v = dotr[i][p];
                v += __shfl_xor_sync(0xffffffffu, v, 1);
                v += __shfl_xor_sync(0xffffffffu, v, 2);
                if ((lane & 3) == 0) {
                    const int row = bm + wm + i * 16 + crow + p * 8;
                    wpart[(size_t)row * 16 + blockIdx.x * 4 + (wid >> 1)] = v;
                }
            }
        return;
    }

#pragma unroll
    for (int i = 0; i < 4; i++) {
        const int r0 = bm + wm + i * 16 + crow;
#pragma unroll
        for (int j = 0; j < 4; j++) {
            const int col = bn + wn + j * 8 + ccol;
            float bx = 0.f, by = 0.f;
            if (HASBIAS) {
                float2 bv = *(const float2*)(bias + col);
                bx = bv.x; by = bv.y;
            }
            float2 o0, o1;
            o0.x = acc[i][j][0] + bx; o0.y = acc[i][j][1] + by;
            o1.x = acc[i][j][2] + bx; o1.y = acc[i][j][3] + by;
            if (RELU) {
                o0.x = fmaxf(o0.x, 0.f); o0.y = fmaxf(o0.y, 0.f);
                o1.x = fmaxf(o1.x, 0.f); o1.y = fmaxf(o1.y, 0.f);
            }
            if (OUT_HL) {
                __nv_bfloat162 h2, l2;
                split_bf16(o0.x, h2.x, l2.x); split_bf16(o0.y, h2.y, l2.y);
                *(__nv_bfloat162*)(Ch + (size_t)r0 * DD + col) = h2;
                *(__nv_bfloat162*)(Cl + (size_t)r0 * DD + col) = l2;
                split_bf16(o1.x, h2.x, l2.x); split_bf16(o1.y, h2.y, l2.y);
                *(__nv_bfloat162*)(Ch + (size_t)(r0 + 8) * DD + col) = h2;
                *(__nv_bfloat162*)(Cl + (size_t)(r0 + 8) * DD + col) = l2;
            } else {
                *(float2*)(C + (size_t)r0 * DD + col) = o0;
                *(float2*)(C + (size_t)(r0 + 8) * DD + col) = o1;
            }
        }
    }
}

// ---------------------------------------------------------------------------
// Downsample: vds[s,:] = sum_f w[4s+f] * value[4s+f,:]; sw[s] = sum_f w.
// ---------------------------------------------------------------------------
__global__ void __launch_bounds__(256) wds_kernel(
    const float* __restrict__ wpart, const float* __restrict__ value,
    __nv_bfloat16* __restrict__ vh, __nv_bfloat16* __restrict__ vl,
    float* __restrict__ sw)
{
    const int s = blockIdx.x;
    const int tid = threadIdx.x;
    __shared__ float wp[64];
    __shared__ float wf[4];
    if (tid < 64) wp[tid] = wpart[(size_t)s * 64 + tid];
    __syncthreads();
    if (tid < 4) {
        float a = 0.f;
#pragma unroll
        for (int p = 0; p < 16; p++) a += wp[tid * 16 + p];
        wf[tid] = a;
    }
    __syncthreads();
    const float w0 = wf[0], w1 = wf[1], w2 = wf[2], w3 = wf[3];
    if (tid == 0) sw[s] = w0 + w1 + w2 + w3;

    const float* vr = value + (size_t)s * 4 * DD;
    const size_t o = (size_t)s * DD;
#pragma unroll
    for (int u = 0; u < 2; u++) {
        const int d = tid + u * 256;
        float x = w0 * vr[d] + w1 * vr[DD + d] + w2 * vr[2 * DD + d] + w3 * vr[3 * DD + d];
        __nv_bfloat16 h, l;
        split_bf16(x, h, l);
        vh[o + d] = h;
        vl[o + d] = l;
    }
}

// ---------------------------------------------------------------------------
// warp reduction
// ---------------------------------------------------------------------------
__device__ __forceinline__ float warp_sum(float x) {
#pragma unroll
    for (int o = 16; o > 0; o >>= 1) x += __shfl_xor_sync(0xffffffffu, x, o);
    return x;
}

// ---------------------------------------------------------------------------
// LN1: r = q + ao + sw*b_v; out1 = LN(r) (fp32 + bf16 hi/lo)
// ---------------------------------------------------------------------------
__global__ void __launch_bounds__(256) attn_ln_kernel(
    const float* __restrict__ q, const float* __restrict__ ao,
    const float* __restrict__ sw, const float* __restrict__ bv,
    const float* __restrict__ gamma, const float* __restrict__ beta,
    float* __restrict__ out,
    __nv_bfloat16* __restrict__ outh, __nv_bfloat16* __restrict__ outl)
{
    const int row = blockIdx.x;
    const int tid = threadIdx.x;
    const int lane = tid & 31, wid = tid >> 5;
    const size_t off = (size_t)row * DD;
    const float swv = sw[row];

    float r0 = q[off + tid]       + ao[off + tid]       + swv * bv[tid];
    float r1 = q[off + tid + 256] + ao[off + tid + 256] + swv * bv[tid + 256];

    float s = warp_sum(r0 + r1);
    float ss = warp_sum(r0 * r0 + r1 * r1);
    __shared__ float rs[8], rss[8];
    if (lane == 0) { rs[wid] = s; rss[wid] = ss; }
    __syncthreads();
    __shared__ float mv[2];
    if (tid == 0) {
        float S = 0.f, SS = 0.f;
#pragma unroll
        for (int i = 0; i < 8; i++) { S += rs[i]; SS += rss[i]; }
        float mean = S * (1.f / 512.f);
        float var = SS * (1.f / 512.f) - mean * mean;
        mv[0] = mean; mv[1] = rsqrtf(var + EPS);
    }
    __syncthreads();
    const float mean = mv[0], inv = mv[1];
    float y0 = (r0 - mean) * inv * gamma[tid]       + beta[tid];
    float y1 = (r1 - mean) * inv * gamma[tid + 256] + beta[tid + 256];
    out[off + tid] = y0;
    out[off + tid + 256] = y1;
    __nv_bfloat16 h, l;
    split_bf16(y0, h, l); outh[off + tid] = h;       outl[off + tid] = l;
    split_bf16(y1, h, l); outh[off + tid + 256] = h; outl[off + tid + 256] = l;
}

// ---------------------------------------------------------------------------
// Fused residual + LayerNorm2 -> output
// ---------------------------------------------------------------------------
__global__ void __launch_bounds__(256) resid_ln_kernel(
    const float* __restrict__ a, const float* __restrict__ f,
    const float* __restrict__ gamma, const float* __restrict__ beta,
    float* __restrict__ out)
{
    const int row = blockIdx.x;
    const int tid = threadIdx.x;
    const int lane = tid & 31, wid = tid >> 5;
    const size_t off = (size_t)row * DD;

    float r0 = a[off + tid]       + f[off + tid];
    float r1 = a[off + tid + 256] + f[off + tid + 256];

    float s = warp_sum(r0 + r1);
    float ss = warp_sum(r0 * r0 + r1 * r1);
    __shared__ float rs[8], rss[8];
    if (lane == 0) { rs[wid] = s; rss[wid] = ss; }
    __syncthreads();
    __shared__ float mv[2];
    if (tid == 0) {
        float S = 0.f, SS = 0.f;
#pragma unroll
        for (int i = 0; i < 8; i++) { S += rs[i]; SS += rss[i]; }
        float mean = S * (1.f / 512.f);
        float var = SS * (1.f / 512.f) - mean * mean;
        mv[0] = mean; mv[1] = rsqrtf(var + EPS);
    }
    __syncthreads();
    const float mean = mv[0], inv = mv[1];
    out[off + tid]       = (r0 - mean) * inv * gamma[tid]       + beta[tid];
    out[off + tid + 256] = (r1 - mean) * inv * gamma[tid + 256] + beta[tid + 256];
}

// ---------------------------------------------------------------------------
// Launch
// ---------------------------------------------------------------------------
extern "C" void kernel_launch(void* const* d_in, const int* in_sizes, int n_in,
                              void* d_out, int out_size)
{
    const float* query  = (const float*)d_in[0];
    const float* key    = (const float*)d_in[1];
    const float* value  = (const float*)d_in[2];
    const float* w_q    = (const float*)d_in[3];
    const float* b_q    = (const float*)d_in[4];
    const float* w_k    = (const float*)d_in[5];
    const float* b_k    = (const float*)d_in[6];
    const float* w_v    = (const float*)d_in[7];
    const float* b_v    = (const float*)d_in[8];
    const float* ln1_g  = (const float*)d_in[9];
    const float* ln1_b  = (const float*)d_in[10];
    const float* ln2_g  = (const float*)d_in[11];
    const float* ln2_b  = (const float*)d_in[12];
    const float* ffn_w1 = (const float*)d_in[13];
    const float* ffn_b1 = (const float*)d_in[14];
    const float* ffn_w2 = (const float*)d_in[15];
    const float* ffn_b2 = (const float*)d_in[16];
    float* out = (float*)d_out;

    void* sp = nullptr;
    cudaGetSymbolAddress(&sp, g_scratch);
    float* s = (float*)sp;
    float* g_q    = s + F_Q;
    float* g_ao   = s + F_AO;
    float* g_out1 = s + F_O1;
    float* g_ffn  = s + F_FF;
    float* g_wp   = s + F_WP;
    float* g_sw   = s + F_SW;

    void* ap = nullptr;
    cudaGetSymbolAddress(&ap, g_act);
    __nv_bfloat16* a = (__nv_bfloat16*)ap;
    __nv_bfloat16* qh  = a + B_QH;  __nv_bfloat16* ql  = a + B_QL;
    __nv_bfloat16* kh  = a + B_KH;  __nv_bfloat16* kl  = a + B_KL;
    __nv_bfloat16* vh  = a + B_VH;  __nv_bfloat16* vl  = a + B_VL;
    __nv_bfloat16* o1h = a + B_O1H; __nv_bfloat16* o1l = a + B_O1L;
    __nv_bfloat16* hh  = a + B_HH;  __nv_bfloat16* hl  = a + B_HL;

    void* wp = nullptr;
    cudaGetSymbolAddress(&wp, g_wsplit);
    __nv_bfloat16* w = (__nv_bfloat16*)wp;
    const size_t WSZ = 512u * 512u;
    __nv_bfloat16* wqh = w + 0 * 2 * WSZ; __nv_bfloat16* wql = wqh + WSZ;
    __nv_bfloat16* wkh = w + 1 * 2 * WSZ; __nv_bfloat16* wkl = wkh + WSZ;
    __nv_bfloat16* wvh = w + 2 * 2 * WSZ; __nv_bfloat16* wvl = wvh + WSZ;
    __nv_bfloat16* f1h = w + 3 * 2 * WSZ; __nv_bfloat16* f1l = f1h + WSZ;
    __nv_bfloat16* f2h = w + 4 * 2 * WSZ; __nv_bfloat16* f2l = f2h + WSZ;

    cudaFuncSetAttribute((const void*)gemm_hl<true,  false, false, true >, cudaFuncAttributeMaxDynamicSharedMemorySize, GEMM_SMEM);
    cudaFuncSetAttribute((const void*)gemm_hl<true,  false, true,  true >, cudaFuncAttributeMaxDynamicSharedMemorySize, GEMM_SMEM);
    cudaFuncSetAttribute((const void*)gemm_hl<false, false, false, false>, cudaFuncAttributeMaxDynamicSharedMemorySize, GEMM_SMEM);
    cudaFuncSetAttribute((const void*)gemm_hl<true,  true,  false, true >, cudaFuncAttributeMaxDynamicSharedMemorySize, GEMM_SMEM);
    cudaFuncSetAttribute((const void*)gemm_hl<false, false, false, true >, cudaFuncAttributeMaxDynamicSharedMemorySize, GEMM_SMEM);

    const dim3 blk(256);

    prep_weight5<<<dim3(16, 16, 5), dim3(32, 8)>>>(w_q, w_k, w_v, ffn_w1, ffn_w2, w);
    f32_to_hl<<<NQ  * DD / 1024, blk>>>((const float4*)query, (uint2*)qh, (uint2*)ql);
    f32_to_hl<<<NKV * DD / 1024, blk>>>((const float4*)key,   (uint2*)kh, (uint2*)kl);

    const dim3 grid_q(DD / 128, NQ / 128);   // 4 x 64
    const dim3 grid_kv(DD / 128, NKV / 128); // 4 x 256

    // Q projection
    gemm_hl<true, false, false, true><<<grid_q, blk, GEMM_SMEM>>>(
        qh, ql, wqh, wql, b_q, g_q, nullptr, nullptr, nullptr, nullptr);

    // K projection with fused q.k dot -> w partials
    gemm_hl<true, false, true, true><<<grid_kv, blk, GEMM_SMEM>>>(
        kh, kl, wkh, wkl, b_k, nullptr, nullptr, nullptr, g_q, g_wp);

    // downsample raw value by w
    wds_kernel<<<NQ, blk>>>(g_wp, value, vh, vl, g_sw);

    // V projection on downsampled rows
    gemm_hl<false, false, false, false><<<grid_q, blk, GEMM_SMEM>>>(
        vh, vl, wvh, wvl, nullptr, g_ao, nullptr, nullptr, nullptr, nullptr);

    // LN1
    attn_ln_kernel<<<NQ, blk>>>(g_q, g_ao, g_sw, b_v, ln1_g, ln1_b, g_out1, o1h, o1l);

    // FFN
    gemm_hl<true, true, false, true><<<grid_q, blk, GEMM_SMEM>>>(
        o1h, o1l, f1h, f1l, ffn_b1, nullptr, hh, hl, nullptr, nullptr);
    gemm_hl<false, false, false, true><<<grid_q, blk, GEMM_SMEM>>>(
        hh, hl, f2h, f2l, ffn_b2, g_ffn, nullptr, nullptr, nullptr, nullptr);

    resid_ln_kernel<<<NQ, blk>>>(g_out1, g_ffn, ln2_g, ln2_b, out);
}